// round 12
// baseline (speedup 1.0000x reference)
#include <cuda_runtime.h>
#include <cuda_bf16.h>
#include <cstdint>

// ---------------------------------------------------------------------------
// GroupedQueryAttention — Round 12: GEMM warp tiles widened to 64x64
// (4 warps / 128x128 CTA, MMA:ldsm 6:1). Attention unchanged from R11.
// ---------------------------------------------------------------------------

#define SEQ      2048
#define DIM      2048
#define KVDIM    512
#define NHEADS   32
#define NKV      8
#define GROUP    4
#define HDIM     64
#define GK       2048

// fp32 scratch (V only)
__device__ float g_V[SEQ * KVDIM];

// bf16 split scratch
__device__ __nv_bfloat16 g_xh[SEQ * DIM];
__device__ __nv_bfloat16 g_xl[SEQ * DIM];
__device__ __nv_bfloat16 g_Oh[SEQ * DIM];
__device__ __nv_bfloat16 g_Ol[SEQ * DIM];
__device__ __nv_bfloat16 g_wqhT[DIM * DIM];
__device__ __nv_bfloat16 g_wqlT[DIM * DIM];
__device__ __nv_bfloat16 g_wkhT[KVDIM * DIM];
__device__ __nv_bfloat16 g_wklT[KVDIM * DIM];
__device__ __nv_bfloat16 g_wvhT[KVDIM * DIM];
__device__ __nv_bfloat16 g_wvlT[KVDIM * DIM];
__device__ __nv_bfloat16 g_wohT[DIM * DIM];
__device__ __nv_bfloat16 g_wolT[DIM * DIM];

// attention operands
__device__ __nv_bfloat16 g_Qh[SEQ * DIM];     // rope applied, *0.125*log2(e)
__device__ __nv_bfloat16 g_Ql[SEQ * DIM];
__device__ __nv_bfloat16 g_Kh[SEQ * KVDIM];   // rope applied
__device__ __nv_bfloat16 g_Kl[SEQ * KVDIM];
__device__ __nv_bfloat16 g_Vth[KVDIM * SEQ];  // V transposed [512][2048]
__device__ __nv_bfloat16 g_Vtl[KVDIM * SEQ];

// ---------------------------------------------------------------------------
// PTX helpers
// ---------------------------------------------------------------------------
__device__ __forceinline__ uint32_t smem_u32(const void* p) {
    uint32_t a;
    asm("{ .reg .u64 t; cvta.to.shared.u64 t, %1; cvt.u32.u64 %0, t; }"
        : "=r"(a) : "l"(p));
    return a;
}

#define CP_ASYNC16(dst_u32, src_ptr) \
    asm volatile("cp.async.cg.shared.global [%0], [%1], 16;" \
                 :: "r"(dst_u32), "l"(src_ptr))
#define CP_COMMIT() asm volatile("cp.async.commit_group;" ::: "memory")
#define CP_WAIT1()  asm volatile("cp.async.wait_group 1;" ::: "memory")
#define CP_WAIT0()  asm volatile("cp.async.wait_group 0;" ::: "memory")

__device__ __forceinline__ void ldsm_x4(uint32_t* r, uint32_t addr) {
    asm volatile("ldmatrix.sync.aligned.m8n8.x4.shared.b16 {%0,%1,%2,%3}, [%4];"
                 : "=r"(r[0]), "=r"(r[1]), "=r"(r[2]), "=r"(r[3]) : "r"(addr));
}

__device__ __forceinline__ void mma16816(float* c, const uint32_t* a,
                                         const uint32_t* b) {
    asm volatile(
        "mma.sync.aligned.m16n8k16.row.col.f32.bf16.bf16.f32 "
        "{%0,%1,%2,%3}, {%4,%5,%6,%7}, {%8,%9}, {%0,%1,%2,%3};"
        : "+f"(c[0]), "+f"(c[1]), "+f"(c[2]), "+f"(c[3])
        : "r"(a[0]), "r"(a[1]), "r"(a[2]), "r"(a[3]), "r"(b[0]), "r"(b[1]));
}

__device__ __forceinline__ float exp2a(float x) {
    float y;
    asm("ex2.approx.ftz.f32 %0, %1;" : "=f"(y) : "f"(x));
    return y;
}

__device__ __forceinline__ void split2(float a, float b,
                                       uint32_t& hi, uint32_t& lo) {
    __nv_bfloat162 H = __floats2bfloat162_rn(a, b);
    float2 Hf = __bfloat1622float2(H);
    __nv_bfloat162 L = __floats2bfloat162_rn(a - Hf.x, b - Hf.y);
    hi = *reinterpret_cast<uint32_t*>(&H);
    lo = *reinterpret_cast<uint32_t*>(&L);
}

// ---------------------------------------------------------------------------
// GEMM tiling: 128x128 CTA tile, 4 warps (2x2 grid of 64x64 warp tiles),
// KCH=32, 2-stage cp.async, 2 CTAs/SM.
// ---------------------------------------------------------------------------
#define KCH      32
#define LDS_H    40
#define TILE_B   (128 * LDS_H * 2)
#define STAGE_B  (4 * TILE_B)          // 40960
#define GEMM_SMEM (2 * STAGE_B)        // 81920

__device__ __forceinline__ void issue_stage(
    const __nv_bfloat16* __restrict__ Ah, const __nv_bfloat16* __restrict__ Al,
    const __nv_bfloat16* __restrict__ Bh, const __nv_bfloat16* __restrict__ Bl,
    int m0, int n0, int k0, uint32_t s_u32, int tid)
{
    const __nv_bfloat16* gp[4] = { Ah, Al, Bh, Bl };
    const int r0[4] = { m0, m0, n0, n0 };
    #pragma unroll
    for (int p = 0; p < 4; p++) {
        #pragma unroll
        for (int i = 0; i < 4; i++) {
            int e   = tid + i * 128;
            int row = e >> 2;
            int q   = e & 3;
            const __nv_bfloat16* src =
                gp[p] + (size_t)(r0[p] + row) * GK + k0 + q * 8;
            uint32_t dst = s_u32 + p * TILE_B + row * (LDS_H * 2) + q * 16;
            CP_ASYNC16(dst, src);
        }
    }
}

// acc[4][8][4]: mt 0..3 (64 rows), n8 0..7 (64 cols)
__device__ __forceinline__ void gemm_mainloop(
    const __nv_bfloat16* Ah, const __nv_bfloat16* Al,
    const __nv_bfloat16* Bh, const __nv_bfloat16* Bl,
    int m0, int n0, uint32_t sm0, int tid, int wm, int wn,
    int lrow, int lcol, float acc[4][8][4])
{
    const int NC = GK / KCH;

    issue_stage(Ah, Al, Bh, Bl, m0, n0, 0, sm0, tid);
    CP_COMMIT();

    for (int c = 0; c < NC; c++) {
        if (c + 1 < NC) {
            issue_stage(Ah, Al, Bh, Bl, m0, n0, (c + 1) * KCH,
                        sm0 + ((c + 1) & 1) * STAGE_B, tid);
            CP_COMMIT();
            CP_WAIT1();
        } else {
            CP_WAIT0();
        }
        __syncthreads();

        const uint32_t sb  = sm0 + (c & 1) * STAGE_B;
        const uint32_t sAh = sb + 0 * TILE_B;
        const uint32_t sAl = sb + 1 * TILE_B;
        const uint32_t sBh = sb + 2 * TILE_B;
        const uint32_t sBl = sb + 3 * TILE_B;

        #pragma unroll
        for (int kk = 0; kk < 2; kk++) {
            uint32_t ah[4][4], al[4][4];
            #pragma unroll
            for (int mt = 0; mt < 4; mt++) {
                uint32_t off =
                    (uint32_t)((wm * 64 + mt * 16 + lrow) * LDS_H + kk * 16 + lcol) * 2;
                ldsm_x4(ah[mt], sAh + off);
                ldsm_x4(al[mt], sAl + off);
            }
            #pragma unroll
            for (int nt = 0; nt < 4; nt++) {
                uint32_t off =
                    (uint32_t)((wn * 64 + nt * 16 + lrow) * LDS_H + kk * 16 + lcol) * 2;
                uint32_t th[4], tl[4];
                ldsm_x4(th, sBh + off);
                ldsm_x4(tl, sBl + off);
                uint32_t b0h[2] = { th[0], th[2] }, b1h[2] = { th[1], th[3] };
                uint32_t b0l[2] = { tl[0], tl[2] }, b1l[2] = { tl[1], tl[3] };
                #pragma unroll
                for (int mt = 0; mt < 4; mt++) {
                    mma16816(acc[mt][2 * nt],     ah[mt], b0h);
                    mma16816(acc[mt][2 * nt],     ah[mt], b0l);
                    mma16816(acc[mt][2 * nt],     al[mt], b0h);
                    mma16816(acc[mt][2 * nt + 1], ah[mt], b1h);
                    mma16816(acc[mt][2 * nt + 1], ah[mt], b1l);
                    mma16816(acc[mt][2 * nt + 1], al[mt], b1h);
                }
            }
        }
        __syncthreads();
    }
}

// ---------------------------------------------------------------------------
// Fused QKV GEMM (+rope+split epilogues)
// ---------------------------------------------------------------------------
#define LN10K_32  0.2878231366f
#define QSCALE    0.1803368801f    // 0.125 * log2(e)

__global__ void __launch_bounds__(128, 2)
qkv_gemm_kernel(const __nv_bfloat16* __restrict__ xh,
                const __nv_bfloat16* __restrict__ xl,
                const __nv_bfloat16* __restrict__ wqh,
                const __nv_bfloat16* __restrict__ wql,
                const __nv_bfloat16* __restrict__ wkh,
                const __nv_bfloat16* __restrict__ wkl,
                const __nv_bfloat16* __restrict__ wvh,
                const __nv_bfloat16* __restrict__ wvl,
                __nv_bfloat16* __restrict__ Qh, __nv_bfloat16* __restrict__ Ql,
                __nv_bfloat16* __restrict__ Kh, __nv_bfloat16* __restrict__ Kl,
                float* __restrict__ V)
{
    extern __shared__ char smem[];
    const uint32_t sm0 = smem_u32(smem);
    const int tid  = threadIdx.x;
    const int wid  = tid >> 5;
    const int lane = tid & 31;
    const int wm   = wid & 1;              // 2 m-blocks of 64
    const int wn   = wid >> 1;             // 2 n-blocks of 64
    const int m0   = blockIdx.y * 128;
    const int bx   = blockIdx.x;

    int mode, n0;
    const __nv_bfloat16 *Bh, *Bl;
    if (bx < 16)      { mode = 0; n0 = bx * 128;        Bh = wqh; Bl = wql; }
    else if (bx < 20) { mode = 1; n0 = (bx - 16) * 128; Bh = wkh; Bl = wkl; }
    else              { mode = 2; n0 = (bx - 20) * 128; Bh = wvh; Bl = wvl; }

    const int lrow = (lane & 7) + ((lane >> 3) & 1) * 8;
    const int lcol = (lane >> 4) * 8;

    float acc[4][8][4];
    #pragma unroll
    for (int mt = 0; mt < 4; mt++)
        #pragma unroll
        for (int n8 = 0; n8 < 8; n8++)
            #pragma unroll
            for (int j = 0; j < 4; j++) acc[mt][n8][j] = 0.f;

    gemm_mainloop(xh, xl, Bh, Bl, m0, n0, sm0, tid, wm, wn, lrow, lcol, acc);

    const int cr = lane >> 2;
    const int cc = (lane & 3) * 2;

    if (mode == 2) {
        #pragma unroll
        for (int mt = 0; mt < 4; mt++)
            #pragma unroll
            for (int n8 = 0; n8 < 8; n8++) {
                float* base = V + (size_t)(m0 + wm * 64 + mt * 16 + cr) * KVDIM
                                + n0 + wn * 64 + n8 * 8 + cc;
                *reinterpret_cast<float2*>(base) =
                    make_float2(acc[mt][n8][0], acc[mt][n8][1]);
                *reinterpret_cast<float2*>(base + 8 * (size_t)KVDIM) =
                    make_float2(acc[mt][n8][2], acc[mt][n8][3]);
            }
        return;
    }

    const float scale = (mode == 0) ? QSCALE : 1.0f;
    const int   ldo   = (mode == 0) ? DIM : KVDIM;
    __nv_bfloat16* OH = (mode == 0) ? Qh : Kh;
    __nv_bfloat16* OL = (mode == 0) ? Ql : Kl;

    #pragma unroll
    for (int mt = 0; mt < 4; mt++) {
        const int r0 = m0 + wm * 64 + mt * 16 + cr;
        #pragma unroll
        for (int n8 = 0; n8 < 4; n8++) {
            const int d0 = n8 * 8 + cc;
            const float f0 = __expf(-(float)d0 * LN10K_32);
            const float f1 = __expf(-(float)(d0 + 1) * LN10K_32);
            #pragma unroll
            for (int half = 0; half < 2; half++) {
                const int r = r0 + half * 8;
                float c0, s0, c1, s1;
                sincosf((float)r * f0, &s0, &c0);
                sincosf((float)r * f1, &s1, &c1);
                const float x1a = acc[mt][n8][half * 2 + 0];
                const float x1b = acc[mt][n8][half * 2 + 1];
                const float x2a = acc[mt][n8 + 4][half * 2 + 0];
                const float x2b = acc[mt][n8 + 4][half * 2 + 1];
                const float lo0 = (x1a * c0 - x2a * s0) * scale;
                const float lo1 = (x1b * c1 - x2b * s1) * scale;
                const float hi0 = (x2a * c0 + x1a * s0) * scale;
                const float hi1 = (x2b * c1 + x1b * s1) * scale;
                const size_t off = (size_t)r * ldo + n0 + wn * 64 + n8 * 8 + cc;
                uint32_t H, L;
                split2(lo0, lo1, H, L);
                *reinterpret_cast<uint32_t*>(OH + off) = H;
                *reinterpret_cast<uint32_t*>(OL + off) = L;
                split2(hi0, hi1, H, L);
                *reinterpret_cast<uint32_t*>(OH + off + 32) = H;
                *reinterpret_cast<uint32_t*>(OL + off + 32) = L;
            }
        }
    }
}

// ---------------------------------------------------------------------------
// O-projection GEMM
// ---------------------------------------------------------------------------
__global__ void __launch_bounds__(128, 2)
gemm3_kernel(const __nv_bfloat16* __restrict__ Ah,
             const __nv_bfloat16* __restrict__ Al,
             const __nv_bfloat16* __restrict__ BhT,
             const __nv_bfloat16* __restrict__ BlT,
             float* __restrict__ C, int ldc)
{
    extern __shared__ char smem[];
    const uint32_t sm0 = smem_u32(smem);
    const int tid  = threadIdx.x;
    const int wid  = tid >> 5;
    const int lane = tid & 31;
    const int wm   = wid & 1;
    const int wn   = wid >> 1;
    const int m0   = blockIdx.y * 128;
    const int n0   = blockIdx.x * 128;

    const int lrow = (lane & 7) + ((lane >> 3) & 1) * 8;
    const int lcol = (lane >> 4) * 8;

    float acc[4][8][4];
    #pragma unroll
    for (int mt = 0; mt < 4; mt++)
        #pragma unroll
        for (int n8 = 0; n8 < 8; n8++)
            #pragma unroll
            for (int j = 0; j < 4; j++) acc[mt][n8][j] = 0.f;

    gemm_mainloop(Ah, Al, BhT, BlT, m0, n0, sm0, tid, wm, wn, lrow, lcol, acc);

    const int cr = lane >> 2;
    const int cc = (lane & 3) * 2;
    #pragma unroll
    for (int mt = 0; mt < 4; mt++) {
        #pragma unroll
        for (int n8 = 0; n8 < 8; n8++) {
            float* base = C + (size_t)(m0 + wm * 64 + mt * 16 + cr) * ldc
                            + n0 + wn * 64 + n8 * 8 + cc;
            *reinterpret_cast<float2*>(base) =
                make_float2(acc[mt][n8][0], acc[mt][n8][1]);
            *reinterpret_cast<float2*>(base + 8 * (size_t)ldc) =
                make_float2(acc[mt][n8][2], acc[mt][n8][3]);
        }
    }
}

// ---------------------------------------------------------------------------
// x split (element-wise)
// ---------------------------------------------------------------------------
__global__ void split_kernel(const float* __restrict__ in,
                             __nv_bfloat16* __restrict__ hi,
                             __nv_bfloat16* __restrict__ lo)
{
    int i = (blockIdx.x * 256 + threadIdx.x) * 4;
    float4 v = *reinterpret_cast<const float4*>(in + i);
    float vv[4] = { v.x, v.y, v.z, v.w };
    __nv_bfloat16 h[4], l[4];
    #pragma unroll
    for (int j = 0; j < 4; j++) {
        h[j] = __float2bfloat16(vv[j]);
        l[j] = __float2bfloat16(vv[j] - __bfloat162float(h[j]));
    }
    *reinterpret_cast<uint2*>(hi + i) = *reinterpret_cast<uint2*>(h);
    *reinterpret_cast<uint2*>(lo + i) = *reinterpret_cast<uint2*>(l);
}

// ---------------------------------------------------------------------------
// All weight transpose-splits in ONE launch
// ---------------------------------------------------------------------------
__global__ void wsplit_all_kernel(
    const float* __restrict__ wq, const float* __restrict__ wk,
    const float* __restrict__ wv, const float* __restrict__ wo,
    __nv_bfloat16* __restrict__ wqh, __nv_bfloat16* __restrict__ wql,
    __nv_bfloat16* __restrict__ wkh, __nv_bfloat16* __restrict__ wkl,
    __nv_bfloat16* __restrict__ wvh, __nv_bfloat16* __restrict__ wvl,
    __nv_bfloat16* __restrict__ woh, __nv_bfloat16* __restrict__ wol)
{
    __shared__ float t[32][33];
    int bid = blockIdx.x;
    const float* w;
    __nv_bfloat16 *hiT, *loT;
    int N, local;
    if (bid < 4096)      { w = wq; hiT = wqh; loT = wql; N = DIM;   local = bid; }
    else if (bid < 5120) { w = wk; hiT = wkh; loT = wkl; N = KVDIM; local = bid - 4096; }
    else if (bid < 6144) { w = wv; hiT = wvh; loT = wvl; N = KVDIM; local = bid - 5120; }
    else                 { w = wo; hiT = woh; loT = wol; N = DIM;   local = bid - 6144; }
    const int nbx = N / 32;
    const int n0 = (local % nbx) * 32;
    const int k0 = (local / nbx) * 32;
    const int tx = threadIdx.x, ty = threadIdx.y;
    #pragma unroll
    for (int r = 0; r < 4; r++)
        t[ty + 8 * r][tx] = w[(size_t)(k0 + ty + 8 * r) * N + n0 + tx];
    __syncthreads();
    #pragma unroll
    for (int r = 0; r < 4; r++) {
        int row = ty + 8 * r;
        float v = t[tx][row];
        __nv_bfloat16 h = __float2bfloat16(v);
        __nv_bfloat16 l = __float2bfloat16(v - __bfloat162float(h));
        size_t o = (size_t)(n0 + row) * GK + k0 + tx;
        hiT[o] = h;
        loT[o] = l;
    }
}

// ---------------------------------------------------------------------------
// V transpose-split
// ---------------------------------------------------------------------------
__global__ void vtsplit_kernel(const float* __restrict__ V,
                               __nv_bfloat16* __restrict__ Vth,
                               __nv_bfloat16* __restrict__ Vtl)
{
    __shared__ float t[32][33];
    const int sB = blockIdx.x * 32;
    const int dB = blockIdx.y * 32;
    const int tx = threadIdx.x, ty = threadIdx.y;
    #pragma unroll
    for (int r = 0; r < 4; r++)
        t[ty + 8 * r][tx] = V[(size_t)(sB + ty + 8 * r) * KVDIM + dB + tx];
    __syncthreads();
    #pragma unroll
    for (int r = 0; r < 4; r++) {
        int dd = ty + 8 * r;
        float v = t[tx][dd];
        __nv_bfloat16 h = __float2bfloat16(v);
        __nv_bfloat16 l = __float2bfloat16(v - __bfloat162float(h));
        size_t o = (size_t)(dB + dd) * SEQ + sB + tx;
        Vth[o] = h;
        Vtl[o] = l;
    }
}

// ---------------------------------------------------------------------------
// HMMA flash attention — 2 heads per CTA, 256 threads, BQ=128,
// 32 q-rows per warp (mt=2), max-free softmax, 3-term QK and PV.
// (unchanged from R11)
// ---------------------------------------------------------------------------
#define BQ     128
#define BK     64
#define PADH   72
#define ROWB   (PADH * 2)          // 144
#define QATILE (128 * ROWB)        // 18432
#define ATILE  (64 * ROWB)         // 9216
#define ASTAGE (4 * ATILE)         // 36864
#define SM_KV  (4 * QATILE)        // 73728
#define ATT_SMEM (SM_KV + 2 * ASTAGE)   // 147456

__device__ __forceinline__ void att_issue(
    uint32_t sb,
    const __nv_bfloat16* __restrict__ Kh, const __nv_bfloat16* __restrict__ Kl,
    const __nv_bfloat16* __restrict__ Vth, const __nv_bfloat16* __restrict__ Vtl,
    int k0, int kh, int tid)
{
    const size_t kbase  = (size_t)kh * HDIM;
    const size_t vtbase = (size_t)kh * HDIM * SEQ;
    const __nv_bfloat16* gp[4] = { Kh, Kl, Vth, Vtl };
    #pragma unroll
    for (int p = 0; p < 4; p++) {
        #pragma unroll
        for (int i = 0; i < 2; i++) {
            int idx = tid + i * 256;
            int r = idx >> 3, q = idx & 7;
            uint32_t so = (uint32_t)(r * ROWB + q * 16);
            const __nv_bfloat16* src = (p < 2)
                ? gp[p] + (size_t)(k0 + r) * KVDIM + kbase + q * 8
                : gp[p] + vtbase + (size_t)r * SEQ + k0 + q * 8;
            CP_ASYNC16(sb + p * ATILE + so, src);
        }
    }
}

__global__ void __launch_bounds__(256, 1)
attn_mma_kernel(const __nv_bfloat16* __restrict__ Qh,
                const __nv_bfloat16* __restrict__ Ql,
                const __nv_bfloat16* __restrict__ Kh,
                const __nv_bfloat16* __restrict__ Kl,
                const __nv_bfloat16* __restrict__ Vth,
                const __nv_bfloat16* __restrict__ Vtl,
                __nv_bfloat16* __restrict__ Ohi,
                __nv_bfloat16* __restrict__ Olo)
{
    extern __shared__ char smem[];
    const uint32_t s0 = smem_u32(smem);
    const int tid = threadIdx.x, wid = tid >> 5, lane = tid & 31;
    const int hd = wid >> 2;
    const int w  = wid & 3;
    const int h  = blockIdx.y * 2 + hd;
    const int kh = blockIdx.y >> 1;
    const int q0 = blockIdx.x * BQ;
    const int lrow = (lane & 7) + ((lane >> 3) & 1) * 8;
    const int lcol = (lane >> 4) * 8;
    const int gr = lane >> 2, tg = lane & 3;
    const int NT = SEQ / BK;

    #pragma unroll
    for (int b = 0; b < 4; b++) {
        const __nv_bfloat16* src = (b & 1) ? Ql : Qh;
        const int hh = blockIdx.y * 2 + (b >> 1);
        #pragma unroll
        for (int i = 0; i < 4; i++) {
            int idx = tid + i * 256;
            int r = idx >> 3, q = idx & 7;
            CP_ASYNC16(s0 + b * QATILE + (uint32_t)(r * ROWB + q * 16),
                       src + (size_t)(q0 + r) * DIM + hh * HDIM + q * 8);
        }
    }
    att_issue(s0 + SM_KV, Kh, Kl, Vth, Vtl, 0, kh, tid);
    CP_COMMIT();
    CP_WAIT0();
    __syncthreads();

    uint32_t qfh[2][4][4], qfl[2][4][4];
    {
        const uint32_t qb = s0 + (hd * 2) * QATILE;
        #pragma unroll
        for (int mt = 0; mt < 2; mt++)
            #pragma unroll
            for (int kc = 0; kc < 4; kc++) {
                uint32_t off = (uint32_t)((w * 32 + mt * 16 + lrow) * ROWB
                                          + (kc * 16 + lcol) * 2);
                ldsm_x4(qfh[mt][kc], qb + off);
                ldsm_x4(qfl[mt][kc], qb + QATILE + off);
            }
    }

    float acc[2][8][4];
    #pragma unroll
    for (int mt = 0; mt < 2; mt++)
        #pragma unroll
        for (int j = 0; j < 8; j++)
            #pragma unroll
            for (int i = 0; i < 4; i++) acc[mt][j][i] = 0.f;
    float lsum[2][2] = { {0.f, 0.f}, {0.f, 0.f} };

    for (int c = 0; c < NT; c++) {
        if (c + 1 < NT) {
            att_issue(s0 + SM_KV + ((c + 1) & 1) * ASTAGE,
                      Kh, Kl, Vth, Vtl, (c + 1) * BK, kh, tid);
            CP_COMMIT();
            CP_WAIT1();
        } else {
            CP_WAIT0();
        }
        __syncthreads();

        const uint32_t sb  = s0 + SM_KV + (c & 1) * ASTAGE;
        const uint32_t sKh = sb + 0 * ATILE;
        const uint32_t sKl = sb + 1 * ATILE;
        const uint32_t sVh = sb + 2 * ATILE;
        const uint32_t sVl = sb + 3 * ATILE;

        float s[2][8][4];
        #pragma unroll
        for (int mt = 0; mt < 2; mt++)
            #pragma unroll
            for (int j = 0; j < 8; j++)
                #pragma unroll
                for (int i = 0; i < 4; i++) s[mt][j][i] = 0.f;

        #pragma unroll
        for (int kc = 0; kc < 4; kc++) {
            #pragma unroll
            for (int nt = 0; nt < 4; nt++) {
                uint32_t off = (uint32_t)((nt * 16 + lrow) * ROWB + (kc * 16 + lcol) * 2);
                uint32_t th[4], tl[4];
                ldsm_x4(th, sKh + off);
                ldsm_x4(tl, sKl + off);
                uint32_t b0h[2] = { th[0], th[2] }, b1h[2] = { th[1], th[3] };
                uint32_t b0l[2] = { tl[0], tl[2] }, b1l[2] = { tl[1], tl[3] };
                #pragma unroll
                for (int mt = 0; mt < 2; mt++) {
                    mma16816(s[mt][2 * nt],     qfh[mt][kc], b0h);
                    mma16816(s[mt][2 * nt],     qfh[mt][kc], b0l);
                    mma16816(s[mt][2 * nt],     qfl[mt][kc], b0h);
                    mma16816(s[mt][2 * nt + 1], qfh[mt][kc], b1h);
                    mma16816(s[mt][2 * nt + 1], qfh[mt][kc], b1l);
                    mma16816(s[mt][2 * nt + 1], qfl[mt][kc], b1h);
                }
            }
        }

        #pragma unroll
        for (int mt = 0; mt < 2; mt++)
            #pragma unroll
            for (int j = 0; j < 8; j++) {
                s[mt][j][0] = exp2a(s[mt][j][0]);
                s[mt][j][1] = exp2a(s[mt][j][1]);
                s[mt][j][2] = exp2a(s[mt][j][2]);
                s[mt][j][3] = exp2a(s[mt][j][3]);
                lsum[mt][0] += s[mt][j][0] + s[mt][j][1];
                lsum[mt][1] += s[mt][j][2] + s[mt][j][3];
            }

        #pragma unroll
        for (int kc = 0; kc < 4; kc++) {
            uint32_t aph[2][4], apl[2][4];
            #pragma unroll
            for (int mt = 0; mt < 2; mt++) {
                split2(s[mt][2 * kc][0],     s[mt][2 * kc][1],     aph[mt][0], apl[mt][0]);
                split2(s[mt][2 * kc][2],     s[mt][2 * kc][3],     aph[mt][1], apl[mt][1]);
                split2(s[mt][2 * kc + 1][0], s[mt][2 * kc + 1][1], aph[mt][2], apl[mt][2]);
                split2(s[mt][2 * kc + 1][2], s[mt][2 * kc + 1][3], aph[mt][3], apl[mt][3]);
            }
            #pragma unroll
            for (int nt = 0; nt < 4; nt++) {
                uint32_t off = (uint32_t)((nt * 16 + lrow) * ROWB + (kc * 16 + lcol) * 2);
                uint32_t th[4], tl[4];
                ldsm_x4(th, sVh + off);
                ldsm_x4(tl, sVl + off);
                uint32_t b0h[2] = { th[0], th[2] }, b1h[2] = { th[1], th[3] };
                uint32_t b0l[2] = { tl[0], tl[2] }, b1l[2] = { tl[1], tl[3] };
                #pragma unroll
                for (int mt = 0; mt < 2; mt++) {
                    mma16816(acc[mt][2 * nt],     aph[mt], b0h);
                    mma16816(acc[mt][2 * nt],     aph[mt], b0l);
                    mma16816(acc[mt][2 * nt],     apl[mt], b0h);
                    mma16816(acc[mt][2 * nt + 1], aph[mt], b1h);
                    mma16816(acc[mt][2 * nt + 1], aph[mt], b1l);
                    mma16816(acc[mt][2 * nt + 1], apl[mt], b1h);
                }
            }
        }
        __syncthreads();
    }

    #pragma unroll
    for (int mt = 0; mt < 2; mt++)
        #pragma unroll
        for (int i = 0; i < 2; i++) {
            lsum[mt][i] += __shfl_xor_sync(0xffffffffu, lsum[mt][i], 1);
            lsum[mt][i] += __shfl_xor_sync(0xffffffffu, lsum[mt][i], 2);
        }

    #pragma unroll
    for (int mt = 0; mt < 2; mt++) {
        const float inv0 = 1.f / lsum[mt][0], inv1 = 1.f / lsum[mt][1];
        #pragma unroll
        for (int j = 0; j < 8; j++) {
            const size_t off0 = (size_t)(q0 + w * 32 + mt * 16 + gr) * DIM
                              + h * HDIM + j * 8 + tg * 2;
            const size_t off1 = off0 + 8 * (size_t)DIM;
            uint32_t H, L;
            split2(acc[mt][j][0] * inv0, acc[mt][j][1] * inv0, H, L);
            *reinterpret_cast<uint32_t*>(Ohi + off0) = H;
            *reinterpret_cast<uint32_t*>(Olo + off0) = L;
            split2(acc[mt][j][2] * inv1, acc[mt][j][3] * inv1, H, L);
            *reinterpret_cast<uint32_t*>(Ohi + off1) = H;
            *reinterpret_cast<uint32_t*>(Olo + off1) = L;
        }
    }
}

// ---------------------------------------------------------------------------
// Launch
// ---------------------------------------------------------------------------
extern "C" void kernel_launch(void* const* d_in, const int* in_sizes, int n_in,
                              void* d_out, int out_size)
{
    const float* x  = (const float*)d_in[0];
    const float* wq = (const float*)d_in[1];
    const float* wk = (const float*)d_in[2];
    const float* wv = (const float*)d_in[3];
    const float* wo = (const float*)d_in[4];
    float* out = (float*)d_out;

    float* Vb;
    cudaGetSymbolAddress((void**)&Vb, g_V);

    __nv_bfloat16 *xh, *xl, *Oh, *Ol;
    __nv_bfloat16 *wqh, *wql, *wkh, *wkl, *wvh, *wvl, *woh, *wol;
    __nv_bfloat16 *qsh, *qsl, *ksh, *ksl, *vth, *vtl;
    cudaGetSymbolAddress((void**)&xh, g_xh);
    cudaGetSymbolAddress((void**)&xl, g_xl);
    cudaGetSymbolAddress((void**)&Oh, g_Oh);
    cudaGetSymbolAddress((void**)&Ol, g_Ol);
    cudaGetSymbolAddress((void**)&wqh, g_wqhT);
    cudaGetSymbolAddress((void**)&wql, g_wqlT);
    cudaGetSymbolAddress((void**)&wkh, g_wkhT);
    cudaGetSymbolAddress((void**)&wkl, g_wklT);
    cudaGetSymbolAddress((void**)&wvh, g_wvhT);
    cudaGetSymbolAddress((void**)&wvl, g_wvlT);
    cudaGetSymbolAddress((void**)&woh, g_wohT);
    cudaGetSymbolAddress((void**)&wol, g_wolT);
    cudaGetSymbolAddress((void**)&qsh, g_Qh);
    cudaGetSymbolAddress((void**)&qsl, g_Ql);
    cudaGetSymbolAddress((void**)&ksh, g_Kh);
    cudaGetSymbolAddress((void**)&ksl, g_Kl);
    cudaGetSymbolAddress((void**)&vth, g_Vth);
    cudaGetSymbolAddress((void**)&vtl, g_Vtl);

    cudaFuncSetAttribute(qkv_gemm_kernel,
        cudaFuncAttributeMaxDynamicSharedMemorySize, GEMM_SMEM);
    cudaFuncSetAttribute(gemm3_kernel,
        cudaFuncAttributeMaxDynamicSharedMemorySize, GEMM_SMEM);
    cudaFuncSetAttribute(attn_mma_kernel,
        cudaFuncAttributeMaxDynamicSharedMemorySize, ATT_SMEM);

    // splits
    split_kernel<<<SEQ * DIM / 1024, 256>>>(x, xh, xl);
    wsplit_all_kernel<<<10240, dim3(32, 8)>>>(
        wq, wk, wv, wo, wqh, wql, wkh, wkl, wvh, wvl, woh, wol);

    // fused QKV projection (128x128 CTA, 4 warps of 64x64)
    qkv_gemm_kernel<<<dim3(24, 16), 128, GEMM_SMEM>>>(
        xh, xl, wqh, wql, wkh, wkl, wvh, wvl,
        qsh, qsl, ksh, ksl, Vb);

    // V transpose-split
    vtsplit_kernel<<<dim3(SEQ / 32, KVDIM / 32), dim3(32, 8)>>>(Vb, vth, vtl);

    // HMMA flash attention (BQ=128, 2 heads / CTA, mt=2)
    attn_mma_kernel<<<dim3(SEQ / BQ, NKV * 2), 256, ATT_SMEM>>>(
        qsh, qsl, ksh, ksl, vth, vtl, Oh, Ol);

    // output projection (128x128 CTA, 4 warps of 64x64)
    gemm3_kernel<<<dim3(DIM / 128, SEQ / 128), 128, GEMM_SMEM>>>(
        Oh, Ol, woh, wol, out, DIM);
}

// round 13
// speedup vs baseline: 1.0227x; 1.0227x over previous
#include <cuda_runtime.h>
#include <cuda_bf16.h>
#include <cstdint>

// ---------------------------------------------------------------------------
// GroupedQueryAttention — Round 13: R11 compute kernels (best config) +
// rewritten split/transpose glue (packed bf16x2 writes, higher MLP).
// ---------------------------------------------------------------------------

#define SEQ      2048
#define DIM      2048
#define KVDIM    512
#define NHEADS   32
#define NKV      8
#define GROUP    4
#define HDIM     64
#define GK       2048

// fp32 scratch (V only)
__device__ float g_V[SEQ * KVDIM];

// bf16 split scratch
__device__ __nv_bfloat16 g_xh[SEQ * DIM];
__device__ __nv_bfloat16 g_xl[SEQ * DIM];
__device__ __nv_bfloat16 g_Oh[SEQ * DIM];
__device__ __nv_bfloat16 g_Ol[SEQ * DIM];
__device__ __nv_bfloat16 g_wqhT[DIM * DIM];
__device__ __nv_bfloat16 g_wqlT[DIM * DIM];
__device__ __nv_bfloat16 g_wkhT[KVDIM * DIM];
__device__ __nv_bfloat16 g_wklT[KVDIM * DIM];
__device__ __nv_bfloat16 g_wvhT[KVDIM * DIM];
__device__ __nv_bfloat16 g_wvlT[KVDIM * DIM];
__device__ __nv_bfloat16 g_wohT[DIM * DIM];
__device__ __nv_bfloat16 g_wolT[DIM * DIM];

// attention operands
__device__ __nv_bfloat16 g_Qh[SEQ * DIM];     // rope applied, *0.125*log2(e)
__device__ __nv_bfloat16 g_Ql[SEQ * DIM];
__device__ __nv_bfloat16 g_Kh[SEQ * KVDIM];   // rope applied
__device__ __nv_bfloat16 g_Kl[SEQ * KVDIM];
__device__ __nv_bfloat16 g_Vth[KVDIM * SEQ];  // V transposed [512][2048]
__device__ __nv_bfloat16 g_Vtl[KVDIM * SEQ];

// ---------------------------------------------------------------------------
// PTX helpers
// ---------------------------------------------------------------------------
__device__ __forceinline__ uint32_t smem_u32(const void* p) {
    uint32_t a;
    asm("{ .reg .u64 t; cvta.to.shared.u64 t, %1; cvt.u32.u64 %0, t; }"
        : "=r"(a) : "l"(p));
    return a;
}

#define CP_ASYNC16(dst_u32, src_ptr) \
    asm volatile("cp.async.cg.shared.global [%0], [%1], 16;" \
                 :: "r"(dst_u32), "l"(src_ptr))
#define CP_COMMIT() asm volatile("cp.async.commit_group;" ::: "memory")
#define CP_WAIT1()  asm volatile("cp.async.wait_group 1;" ::: "memory")
#define CP_WAIT0()  asm volatile("cp.async.wait_group 0;" ::: "memory")

__device__ __forceinline__ void ldsm_x4(uint32_t* r, uint32_t addr) {
    asm volatile("ldmatrix.sync.aligned.m8n8.x4.shared.b16 {%0,%1,%2,%3}, [%4];"
                 : "=r"(r[0]), "=r"(r[1]), "=r"(r[2]), "=r"(r[3]) : "r"(addr));
}

__device__ __forceinline__ void mma16816(float* c, const uint32_t* a,
                                         const uint32_t* b) {
    asm volatile(
        "mma.sync.aligned.m16n8k16.row.col.f32.bf16.bf16.f32 "
        "{%0,%1,%2,%3}, {%4,%5,%6,%7}, {%8,%9}, {%0,%1,%2,%3};"
        : "+f"(c[0]), "+f"(c[1]), "+f"(c[2]), "+f"(c[3])
        : "r"(a[0]), "r"(a[1]), "r"(a[2]), "r"(a[3]), "r"(b[0]), "r"(b[1]));
}

__device__ __forceinline__ float exp2a(float x) {
    float y;
    asm("ex2.approx.ftz.f32 %0, %1;" : "=f"(y) : "f"(x));
    return y;
}

__device__ __forceinline__ void split2(float a, float b,
                                       uint32_t& hi, uint32_t& lo) {
    __nv_bfloat162 H = __floats2bfloat162_rn(a, b);
    float2 Hf = __bfloat1622float2(H);
    __nv_bfloat162 L = __floats2bfloat162_rn(a - Hf.x, b - Hf.y);
    hi = *reinterpret_cast<uint32_t*>(&H);
    lo = *reinterpret_cast<uint32_t*>(&L);
}

// ---------------------------------------------------------------------------
// GEMM tiling: 128x128 CTA tile, 8 warps (4x2 of 32x64), KCH=32,
// 2-stage cp.async, 2 CTAs/SM.  (R11 config — unchanged)
// ---------------------------------------------------------------------------
#define KCH      32
#define LDS_H    40
#define TILE_B   (128 * LDS_H * 2)
#define STAGE_B  (4 * TILE_B)          // 40960
#define GEMM_SMEM (2 * STAGE_B)        // 81920

__device__ __forceinline__ void issue_stage(
    const __nv_bfloat16* __restrict__ Ah, const __nv_bfloat16* __restrict__ Al,
    const __nv_bfloat16* __restrict__ Bh, const __nv_bfloat16* __restrict__ Bl,
    int m0, int n0, int k0, uint32_t s_u32, int tid)
{
    const __nv_bfloat16* gp[4] = { Ah, Al, Bh, Bl };
    const int r0[4] = { m0, m0, n0, n0 };
    #pragma unroll
    for (int p = 0; p < 4; p++) {
        #pragma unroll
        for (int i = 0; i < 2; i++) {
            int e   = tid + i * 256;
            int row = e >> 2;
            int q   = e & 3;
            const __nv_bfloat16* src =
                gp[p] + (size_t)(r0[p] + row) * GK + k0 + q * 8;
            uint32_t dst = s_u32 + p * TILE_B + row * (LDS_H * 2) + q * 16;
            CP_ASYNC16(dst, src);
        }
    }
}

__device__ __forceinline__ void gemm_mainloop(
    const __nv_bfloat16* Ah, const __nv_bfloat16* Al,
    const __nv_bfloat16* Bh, const __nv_bfloat16* Bl,
    int m0, int n0, uint32_t sm0, int tid, int wm, int wn,
    int lrow, int lcol, float acc[2][8][4])
{
    const int NC = GK / KCH;

    issue_stage(Ah, Al, Bh, Bl, m0, n0, 0, sm0, tid);
    CP_COMMIT();

    for (int c = 0; c < NC; c++) {
        if (c + 1 < NC) {
            issue_stage(Ah, Al, Bh, Bl, m0, n0, (c + 1) * KCH,
                        sm0 + ((c + 1) & 1) * STAGE_B, tid);
            CP_COMMIT();
            CP_WAIT1();
        } else {
            CP_WAIT0();
        }
        __syncthreads();

        const uint32_t sb  = sm0 + (c & 1) * STAGE_B;
        const uint32_t sAh = sb + 0 * TILE_B;
        const uint32_t sAl = sb + 1 * TILE_B;
        const uint32_t sBh = sb + 2 * TILE_B;
        const uint32_t sBl = sb + 3 * TILE_B;

        #pragma unroll
        for (int kk = 0; kk < 2; kk++) {
            uint32_t ah[2][4], al[2][4];
            #pragma unroll
            for (int mt = 0; mt < 2; mt++) {
                uint32_t off =
                    (uint32_t)((wm * 32 + mt * 16 + lrow) * LDS_H + kk * 16 + lcol) * 2;
                ldsm_x4(ah[mt], sAh + off);
                ldsm_x4(al[mt], sAl + off);
            }
            #pragma unroll
            for (int nt = 0; nt < 4; nt++) {
                uint32_t off =
                    (uint32_t)((wn * 64 + nt * 16 + lrow) * LDS_H + kk * 16 + lcol) * 2;
                uint32_t th[4], tl[4];
                ldsm_x4(th, sBh + off);
                ldsm_x4(tl, sBl + off);
                uint32_t b0h[2] = { th[0], th[2] }, b1h[2] = { th[1], th[3] };
                uint32_t b0l[2] = { tl[0], tl[2] }, b1l[2] = { tl[1], tl[3] };
                #pragma unroll
                for (int mt = 0; mt < 2; mt++) {
                    mma16816(acc[mt][2 * nt],     ah[mt], b0h);
                    mma16816(acc[mt][2 * nt],     ah[mt], b0l);
                    mma16816(acc[mt][2 * nt],     al[mt], b0h);
                    mma16816(acc[mt][2 * nt + 1], ah[mt], b1h);
                    mma16816(acc[mt][2 * nt + 1], ah[mt], b1l);
                    mma16816(acc[mt][2 * nt + 1], al[mt], b1h);
                }
            }
        }
        __syncthreads();
    }
}

// ---------------------------------------------------------------------------
// Fused QKV GEMM (+rope+split epilogues) — R11 config
// ---------------------------------------------------------------------------
#define LN10K_32  0.2878231366f
#define QSCALE    0.1803368801f    // 0.125 * log2(e)

__global__ void __launch_bounds__(256, 2)
qkv_gemm_kernel(const __nv_bfloat16* __restrict__ xh,
                const __nv_bfloat16* __restrict__ xl,
                const __nv_bfloat16* __restrict__ wqh,
                const __nv_bfloat16* __restrict__ wql,
                const __nv_bfloat16* __restrict__ wkh,
                const __nv_bfloat16* __restrict__ wkl,
                const __nv_bfloat16* __restrict__ wvh,
                const __nv_bfloat16* __restrict__ wvl,
                __nv_bfloat16* __restrict__ Qh, __nv_bfloat16* __restrict__ Ql,
                __nv_bfloat16* __restrict__ Kh, __nv_bfloat16* __restrict__ Kl,
                float* __restrict__ V)
{
    extern __shared__ char smem[];
    const uint32_t sm0 = smem_u32(smem);
    const int tid  = threadIdx.x;
    const int wid  = tid >> 5;
    const int lane = tid & 31;
    const int wm   = wid & 3;
    const int wn   = wid >> 2;
    const int m0   = blockIdx.y * 128;
    const int bx   = blockIdx.x;

    int mode, n0;
    const __nv_bfloat16 *Bh, *Bl;
    if (bx < 16)      { mode = 0; n0 = bx * 128;        Bh = wqh; Bl = wql; }
    else if (bx < 20) { mode = 1; n0 = (bx - 16) * 128; Bh = wkh; Bl = wkl; }
    else              { mode = 2; n0 = (bx - 20) * 128; Bh = wvh; Bl = wvl; }

    const int lrow = (lane & 7) + ((lane >> 3) & 1) * 8;
    const int lcol = (lane >> 4) * 8;

    float acc[2][8][4];
    #pragma unroll
    for (int mt = 0; mt < 2; mt++)
        #pragma unroll
        for (int n8 = 0; n8 < 8; n8++)
            #pragma unroll
            for (int j = 0; j < 4; j++) acc[mt][n8][j] = 0.f;

    gemm_mainloop(xh, xl, Bh, Bl, m0, n0, sm0, tid, wm, wn, lrow, lcol, acc);

    const int cr = lane >> 2;
    const int cc = (lane & 3) * 2;

    if (mode == 2) {
        #pragma unroll
        for (int mt = 0; mt < 2; mt++)
            #pragma unroll
            for (int n8 = 0; n8 < 8; n8++) {
                float* base = V + (size_t)(m0 + wm * 32 + mt * 16 + cr) * KVDIM
                                + n0 + wn * 64 + n8 * 8 + cc;
                *reinterpret_cast<float2*>(base) =
                    make_float2(acc[mt][n8][0], acc[mt][n8][1]);
                *reinterpret_cast<float2*>(base + 8 * (size_t)KVDIM) =
                    make_float2(acc[mt][n8][2], acc[mt][n8][3]);
            }
        return;
    }

    const float scale = (mode == 0) ? QSCALE : 1.0f;
    const int   ldo   = (mode == 0) ? DIM : KVDIM;
    __nv_bfloat16* OH = (mode == 0) ? Qh : Kh;
    __nv_bfloat16* OL = (mode == 0) ? Ql : Kl;

    #pragma unroll
    for (int mt = 0; mt < 2; mt++) {
        const int r0 = m0 + wm * 32 + mt * 16 + cr;
        #pragma unroll
        for (int n8 = 0; n8 < 4; n8++) {
            const int d0 = n8 * 8 + cc;
            const float f0 = __expf(-(float)d0 * LN10K_32);
            const float f1 = __expf(-(float)(d0 + 1) * LN10K_32);
            #pragma unroll
            for (int half = 0; half < 2; half++) {
                const int r = r0 + half * 8;
                float c0, s0, c1, s1;
                sincosf((float)r * f0, &s0, &c0);
                sincosf((float)r * f1, &s1, &c1);
                const float x1a = acc[mt][n8][half * 2 + 0];
                const float x1b = acc[mt][n8][half * 2 + 1];
                const float x2a = acc[mt][n8 + 4][half * 2 + 0];
                const float x2b = acc[mt][n8 + 4][half * 2 + 1];
                const float lo0 = (x1a * c0 - x2a * s0) * scale;
                const float lo1 = (x1b * c1 - x2b * s1) * scale;
                const float hi0 = (x2a * c0 + x1a * s0) * scale;
                const float hi1 = (x2b * c1 + x1b * s1) * scale;
                const size_t off = (size_t)r * ldo + n0 + wn * 64 + n8 * 8 + cc;
                uint32_t H, L;
                split2(lo0, lo1, H, L);
                *reinterpret_cast<uint32_t*>(OH + off) = H;
                *reinterpret_cast<uint32_t*>(OL + off) = L;
                split2(hi0, hi1, H, L);
                *reinterpret_cast<uint32_t*>(OH + off + 32) = H;
                *reinterpret_cast<uint32_t*>(OL + off + 32) = L;
            }
        }
    }
}

// ---------------------------------------------------------------------------
// O-projection GEMM — R11 config
// ---------------------------------------------------------------------------
__global__ void __launch_bounds__(256, 2)
gemm3_kernel(const __nv_bfloat16* __restrict__ Ah,
             const __nv_bfloat16* __restrict__ Al,
             const __nv_bfloat16* __restrict__ BhT,
             const __nv_bfloat16* __restrict__ BlT,
             float* __restrict__ C, int ldc)
{
    extern __shared__ char smem[];
    const uint32_t sm0 = smem_u32(smem);
    const int tid  = threadIdx.x;
    const int wid  = tid >> 5;
    const int lane = tid & 31;
    const int wm   = wid & 3;
    const int wn   = wid >> 2;
    const int m0   = blockIdx.y * 128;
    const int n0   = blockIdx.x * 128;

    const int lrow = (lane & 7) + ((lane >> 3) & 1) * 8;
    const int lcol = (lane >> 4) * 8;

    float acc[2][8][4];
    #pragma unroll
    for (int mt = 0; mt < 2; mt++)
        #pragma unroll
        for (int n8 = 0; n8 < 8; n8++)
            #pragma unroll
            for (int j = 0; j < 4; j++) acc[mt][n8][j] = 0.f;

    gemm_mainloop(Ah, Al, BhT, BlT, m0, n0, sm0, tid, wm, wn, lrow, lcol, acc);

    const int cr = lane >> 2;
    const int cc = (lane & 3) * 2;
    #pragma unroll
    for (int mt = 0; mt < 2; mt++) {
        #pragma unroll
        for (int n8 = 0; n8 < 8; n8++) {
            float* base = C + (size_t)(m0 + wm * 32 + mt * 16 + cr) * ldc
                            + n0 + wn * 64 + n8 * 8 + cc;
            *reinterpret_cast<float2*>(base) =
                make_float2(acc[mt][n8][0], acc[mt][n8][1]);
            *reinterpret_cast<float2*>(base + 8 * (size_t)ldc) =
                make_float2(acc[mt][n8][2], acc[mt][n8][3]);
        }
    }
}

// ---------------------------------------------------------------------------
// x split — 8 floats per thread (2 independent float4 loads, MLP=2)
// ---------------------------------------------------------------------------
__global__ void split_kernel(const float* __restrict__ in,
                             __nv_bfloat16* __restrict__ hi,
                             __nv_bfloat16* __restrict__ lo)
{
    int i = (blockIdx.x * 256 + threadIdx.x) * 8;
    float4 v0 = *reinterpret_cast<const float4*>(in + i);
    float4 v1 = *reinterpret_cast<const float4*>(in + i + 4);
    float vv[8] = { v0.x, v0.y, v0.z, v0.w, v1.x, v1.y, v1.z, v1.w };
    __nv_bfloat16 h[8], l[8];
    #pragma unroll
    for (int j = 0; j < 8; j++) {
        h[j] = __float2bfloat16(vv[j]);
        l[j] = __float2bfloat16(vv[j] - __bfloat162float(h[j]));
    }
    *reinterpret_cast<uint4*>(hi + i) = *reinterpret_cast<uint4*>(h);
    *reinterpret_cast<uint4*>(lo + i) = *reinterpret_cast<uint4*>(l);
}

// ---------------------------------------------------------------------------
// Weight transpose-splits, ONE launch — 64(k) x 32(n) tiles, packed
// bf16x2 writes along k (4B stores, 128B/warp coalesced).
//   wq: 2048 blocks, wk: 512, wv: 512, wo: 2048  (total 5120)
// ---------------------------------------------------------------------------
__global__ void wsplit_all_kernel(
    const float* __restrict__ wq, const float* __restrict__ wk,
    const float* __restrict__ wv, const float* __restrict__ wo,
    __nv_bfloat16* __restrict__ wqh, __nv_bfloat16* __restrict__ wql,
    __nv_bfloat16* __restrict__ wkh, __nv_bfloat16* __restrict__ wkl,
    __nv_bfloat16* __restrict__ wvh, __nv_bfloat16* __restrict__ wvl,
    __nv_bfloat16* __restrict__ woh, __nv_bfloat16* __restrict__ wol)
{
    __shared__ float t[64][33];
    int bid = blockIdx.x;
    const float* w;
    __nv_bfloat16 *hiT, *loT;
    int N, local;
    if (bid < 2048)      { w = wq; hiT = wqh; loT = wql; N = DIM;   local = bid; }
    else if (bid < 2560) { w = wk; hiT = wkh; loT = wkl; N = KVDIM; local = bid - 2048; }
    else if (bid < 3072) { w = wv; hiT = wvh; loT = wvl; N = KVDIM; local = bid - 2560; }
    else                 { w = wo; hiT = woh; loT = wol; N = DIM;   local = bid - 3072; }
    const int nbx = N / 32;
    const int n0 = (local % nbx) * 32;
    const int k0 = (local / nbx) * 64;
    const int tx = threadIdx.x, ty = threadIdx.y;   // (32, 8)

    // load 64 k-rows x 32 n-cols (coalesced 128B rows)
    #pragma unroll
    for (int r = 0; r < 8; r++)
        t[ty + 8 * r][tx] = w[(size_t)(k0 + ty + 8 * r) * N + n0 + tx];
    __syncthreads();

    // write: for each n-row, thread tx emits k-pair (2tx, 2tx+1) as bf16x2
    #pragma unroll
    for (int j = 0; j < 4; j++) {
        int n = ty + 8 * j;
        float a = t[2 * tx][n];
        float b = t[2 * tx + 1][n];
        uint32_t H, L;
        split2(a, b, H, L);
        size_t o = (size_t)(n0 + n) * GK + k0 + 2 * tx;
        *reinterpret_cast<uint32_t*>(hiT + o) = H;
        *reinterpret_cast<uint32_t*>(loT + o) = L;
    }
}

// ---------------------------------------------------------------------------
// V transpose-split — 64(s) x 32(d) tiles, packed bf16x2 writes along s.
//   grid (SEQ/64, KVDIM/32) = (32, 16)
// ---------------------------------------------------------------------------
__global__ void vtsplit_kernel(const float* __restrict__ V,
                               __nv_bfloat16* __restrict__ Vth,
                               __nv_bfloat16* __restrict__ Vtl)
{
    __shared__ float t[64][33];
    const int sB = blockIdx.x * 64;
    const int dB = blockIdx.y * 32;
    const int tx = threadIdx.x, ty = threadIdx.y;   // (32, 8)
    #pragma unroll
    for (int r = 0; r < 8; r++)
        t[ty + 8 * r][tx] = V[(size_t)(sB + ty + 8 * r) * KVDIM + dB + tx];
    __syncthreads();
    #pragma unroll
    for (int j = 0; j < 4; j++) {
        int d = ty + 8 * j;
        float a = t[2 * tx][d];
        float b = t[2 * tx + 1][d];
        uint32_t H, L;
        split2(a, b, H, L);
        size_t o = (size_t)(dB + d) * SEQ + sB + 2 * tx;
        *reinterpret_cast<uint32_t*>(Vth + o) = H;
        *reinterpret_cast<uint32_t*>(Vtl + o) = L;
    }
}

// ---------------------------------------------------------------------------
// HMMA flash attention — R11 config (2 heads/CTA, BQ=128, mt=2, max-free
// softmax, 3-term QK and PV). Unchanged.
// ---------------------------------------------------------------------------
#define BQ     128
#define BK     64
#define PADH   72
#define ROWB   (PADH * 2)          // 144
#define QATILE (128 * ROWB)        // 18432
#define ATILE  (64 * ROWB)         // 9216
#define ASTAGE (4 * ATILE)         // 36864
#define SM_KV  (4 * QATILE)        // 73728
#define ATT_SMEM (SM_KV + 2 * ASTAGE)   // 147456

__device__ __forceinline__ void att_issue(
    uint32_t sb,
    const __nv_bfloat16* __restrict__ Kh, const __nv_bfloat16* __restrict__ Kl,
    const __nv_bfloat16* __restrict__ Vth, const __nv_bfloat16* __restrict__ Vtl,
    int k0, int kh, int tid)
{
    const size_t kbase  = (size_t)kh * HDIM;
    const size_t vtbase = (size_t)kh * HDIM * SEQ;
    const __nv_bfloat16* gp[4] = { Kh, Kl, Vth, Vtl };
    #pragma unroll
    for (int p = 0; p < 4; p++) {
        #pragma unroll
        for (int i = 0; i < 2; i++) {
            int idx = tid + i * 256;
            int r = idx >> 3, q = idx & 7;
            uint32_t so = (uint32_t)(r * ROWB + q * 16);
            const __nv_bfloat16* src = (p < 2)
                ? gp[p] + (size_t)(k0 + r) * KVDIM + kbase + q * 8
                : gp[p] + vtbase + (size_t)r * SEQ + k0 + q * 8;
            CP_ASYNC16(sb + p * ATILE + so, src);
        }
    }
}

__global__ void __launch_bounds__(256, 1)
attn_mma_kernel(const __nv_bfloat16* __restrict__ Qh,
                const __nv_bfloat16* __restrict__ Ql,
                const __nv_bfloat16* __restrict__ Kh,
                const __nv_bfloat16* __restrict__ Kl,
                const __nv_bfloat16* __restrict__ Vth,
                const __nv_bfloat16* __restrict__ Vtl,
                __nv_bfloat16* __restrict__ Ohi,
                __nv_bfloat16* __restrict__ Olo)
{
    extern __shared__ char smem[];
    const uint32_t s0 = smem_u32(smem);
    const int tid = threadIdx.x, wid = tid >> 5, lane = tid & 31;
    const int hd = wid >> 2;
    const int w  = wid & 3;
    const int h  = blockIdx.y * 2 + hd;
    const int kh = blockIdx.y >> 1;
    const int q0 = blockIdx.x * BQ;
    const int lrow = (lane & 7) + ((lane >> 3) & 1) * 8;
    const int lcol = (lane >> 4) * 8;
    const int gr = lane >> 2, tg = lane & 3;
    const int NT = SEQ / BK;

    #pragma unroll
    for (int b = 0; b < 4; b++) {
        const __nv_bfloat16* src = (b & 1) ? Ql : Qh;
        const int hh = blockIdx.y * 2 + (b >> 1);
        #pragma unroll
        for (int i = 0; i < 4; i++) {
            int idx = tid + i * 256;
            int r = idx >> 3, q = idx & 7;
            CP_ASYNC16(s0 + b * QATILE + (uint32_t)(r * ROWB + q * 16),
                       src + (size_t)(q0 + r) * DIM + hh * HDIM + q * 8);
        }
    }
    att_issue(s0 + SM_KV, Kh, Kl, Vth, Vtl, 0, kh, tid);
    CP_COMMIT();
    CP_WAIT0();
    __syncthreads();

    uint32_t qfh[2][4][4], qfl[2][4][4];
    {
        const uint32_t qb = s0 + (hd * 2) * QATILE;
        #pragma unroll
        for (int mt = 0; mt < 2; mt++)
            #pragma unroll
            for (int kc = 0; kc < 4; kc++) {
                uint32_t off = (uint32_t)((w * 32 + mt * 16 + lrow) * ROWB
                                          + (kc * 16 + lcol) * 2);
                ldsm_x4(qfh[mt][kc], qb + off);
                ldsm_x4(qfl[mt][kc], qb + QATILE + off);
            }
    }

    float acc[2][8][4];
    #pragma unroll
    for (int mt = 0; mt < 2; mt++)
        #pragma unroll
        for (int j = 0; j < 8; j++)
            #pragma unroll
            for (int i = 0; i < 4; i++) acc[mt][j][i] = 0.f;
    float lsum[2][2] = { {0.f, 0.f}, {0.f, 0.f} };

    for (int c = 0; c < NT; c++) {
        if (c + 1 < NT) {
            att_issue(s0 + SM_KV + ((c + 1) & 1) * ASTAGE,
                      Kh, Kl, Vth, Vtl, (c + 1) * BK, kh, tid);
            CP_COMMIT();
            CP_WAIT1();
        } else {
            CP_WAIT0();
        }
        __syncthreads();

        const uint32_t sb  = s0 + SM_KV + (c & 1) * ASTAGE;
        const uint32_t sKh = sb + 0 * ATILE;
        const uint32_t sKl = sb + 1 * ATILE;
        const uint32_t sVh = sb + 2 * ATILE;
        const uint32_t sVl = sb + 3 * ATILE;

        float s[2][8][4];
        #pragma unroll
        for (int mt = 0; mt < 2; mt++)
            #pragma unroll
            for (int j = 0; j < 8; j++)
                #pragma unroll
                for (int i = 0; i < 4; i++) s[mt][j][i] = 0.f;

        #pragma unroll
        for (int kc = 0; kc < 4; kc++) {
            #pragma unroll
            for (int nt = 0; nt < 4; nt++) {
                uint32_t off = (uint32_t)((nt * 16 + lrow) * ROWB + (kc * 16 + lcol) * 2);
                uint32_t th[4], tl[4];
                ldsm_x4(th, sKh + off);
                ldsm_x4(tl, sKl + off);
                uint32_t b0h[2] = { th[0], th[2] }, b1h[2] = { th[1], th[3] };
                uint32_t b0l[2] = { tl[0], tl[2] }, b1l[2] = { tl[1], tl[3] };
                #pragma unroll
                for (int mt = 0; mt < 2; mt++) {
                    mma16816(s[mt][2 * nt],     qfh[mt][kc], b0h);
                    mma16816(s[mt][2 * nt],     qfh[mt][kc], b0l);
                    mma16816(s[mt][2 * nt],     qfl[mt][kc], b0h);
                    mma16816(s[mt][2 * nt + 1], qfh[mt][kc], b1h);
                    mma16816(s[mt][2 * nt + 1], qfh[mt][kc], b1l);
                    mma16816(s[mt][2 * nt + 1], qfl[mt][kc], b1h);
                }
            }
        }

        #pragma unroll
        for (int mt = 0; mt < 2; mt++)
            #pragma unroll
            for (int j = 0; j < 8; j++) {
                s[mt][j][0] = exp2a(s[mt][j][0]);
                s[mt][j][1] = exp2a(s[mt][j][1]);
                s[mt][j][2] = exp2a(s[mt][j][2]);
                s[mt][j][3] = exp2a(s[mt][j][3]);
                lsum[mt][0] += s[mt][j][0] + s[mt][j][1];
                lsum[mt][1] += s[mt][j][2] + s[mt][j][3];
            }

        #pragma unroll
        for (int kc = 0; kc < 4; kc++) {
            uint32_t aph[2][4], apl[2][4];
            #pragma unroll
            for (int mt = 0; mt < 2; mt++) {
                split2(s[mt][2 * kc][0],     s[mt][2 * kc][1],     aph[mt][0], apl[mt][0]);
                split2(s[mt][2 * kc][2],     s[mt][2 * kc][3],     aph[mt][1], apl[mt][1]);
                split2(s[mt][2 * kc + 1][0], s[mt][2 * kc + 1][1], aph[mt][2], apl[mt][2]);
                split2(s[mt][2 * kc + 1][2], s[mt][2 * kc + 1][3], aph[mt][3], apl[mt][3]);
            }
            #pragma unroll
            for (int nt = 0; nt < 4; nt++) {
                uint32_t off = (uint32_t)((nt * 16 + lrow) * ROWB + (kc * 16 + lcol) * 2);
                uint32_t th[4], tl[4];
                ldsm_x4(th, sVh + off);
                ldsm_x4(tl, sVl + off);
                uint32_t b0h[2] = { th[0], th[2] }, b1h[2] = { th[1], th[3] };
                uint32_t b0l[2] = { tl[0], tl[2] }, b1l[2] = { tl[1], tl[3] };
                #pragma unroll
                for (int mt = 0; mt < 2; mt++) {
                    mma16816(acc[mt][2 * nt],     aph[mt], b0h);
                    mma16816(acc[mt][2 * nt],     aph[mt], b0l);
                    mma16816(acc[mt][2 * nt],     apl[mt], b0h);
                    mma16816(acc[mt][2 * nt + 1], aph[mt], b1h);
                    mma16816(acc[mt][2 * nt + 1], aph[mt], b1l);
                    mma16816(acc[mt][2 * nt + 1], apl[mt], b1h);
                }
            }
        }
        __syncthreads();
    }

    #pragma unroll
    for (int mt = 0; mt < 2; mt++)
        #pragma unroll
        for (int i = 0; i < 2; i++) {
            lsum[mt][i] += __shfl_xor_sync(0xffffffffu, lsum[mt][i], 1);
            lsum[mt][i] += __shfl_xor_sync(0xffffffffu, lsum[mt][i], 2);
        }

    #pragma unroll
    for (int mt = 0; mt < 2; mt++) {
        const float inv0 = 1.f / lsum[mt][0], inv1 = 1.f / lsum[mt][1];
        #pragma unroll
        for (int j = 0; j < 8; j++) {
            const size_t off0 = (size_t)(q0 + w * 32 + mt * 16 + gr) * DIM
                              + h * HDIM + j * 8 + tg * 2;
            const size_t off1 = off0 + 8 * (size_t)DIM;
            uint32_t H, L;
            split2(acc[mt][j][0] * inv0, acc[mt][j][1] * inv0, H, L);
            *reinterpret_cast<uint32_t*>(Ohi + off0) = H;
            *reinterpret_cast<uint32_t*>(Olo + off0) = L;
            split2(acc[mt][j][2] * inv1, acc[mt][j][3] * inv1, H, L);
            *reinterpret_cast<uint32_t*>(Ohi + off1) = H;
            *reinterpret_cast<uint32_t*>(Olo + off1) = L;
        }
    }
}

// ---------------------------------------------------------------------------
// Launch
// ---------------------------------------------------------------------------
extern "C" void kernel_launch(void* const* d_in, const int* in_sizes, int n_in,
                              void* d_out, int out_size)
{
    const float* x  = (const float*)d_in[0];
    const float* wq = (const float*)d_in[1];
    const float* wk = (const float*)d_in[2];
    const float* wv = (const float*)d_in[3];
    const float* wo = (const float*)d_in[4];
    float* out = (float*)d_out;

    float* Vb;
    cudaGetSymbolAddress((void**)&Vb, g_V);

    __nv_bfloat16 *xh, *xl, *Oh, *Ol;
    __nv_bfloat16 *wqh, *wql, *wkh, *wkl, *wvh, *wvl, *woh, *wol;
    __nv_bfloat16 *qsh, *qsl, *ksh, *ksl, *vth, *vtl;
    cudaGetSymbolAddress((void**)&xh, g_xh);
    cudaGetSymbolAddress((void**)&xl, g_xl);
    cudaGetSymbolAddress((void**)&Oh, g_Oh);
    cudaGetSymbolAddress((void**)&Ol, g_Ol);
    cudaGetSymbolAddress((void**)&wqh, g_wqhT);
    cudaGetSymbolAddress((void**)&wql, g_wqlT);
    cudaGetSymbolAddress((void**)&wkh, g_wkhT);
    cudaGetSymbolAddress((void**)&wkl, g_wklT);
    cudaGetSymbolAddress((void**)&wvh, g_wvhT);
    cudaGetSymbolAddress((void**)&wvl, g_wvlT);
    cudaGetSymbolAddress((void**)&woh, g_wohT);
    cudaGetSymbolAddress((void**)&wol, g_wolT);
    cudaGetSymbolAddress((void**)&qsh, g_Qh);
    cudaGetSymbolAddress((void**)&qsl, g_Ql);
    cudaGetSymbolAddress((void**)&ksh, g_Kh);
    cudaGetSymbolAddress((void**)&ksl, g_Kl);
    cudaGetSymbolAddress((void**)&vth, g_Vth);
    cudaGetSymbolAddress((void**)&vtl, g_Vtl);

    cudaFuncSetAttribute(qkv_gemm_kernel,
        cudaFuncAttributeMaxDynamicSharedMemorySize, GEMM_SMEM);
    cudaFuncSetAttribute(gemm3_kernel,
        cudaFuncAttributeMaxDynamicSharedMemorySize, GEMM_SMEM);
    cudaFuncSetAttribute(attn_mma_kernel,
        cudaFuncAttributeMaxDynamicSharedMemorySize, ATT_SMEM);

    // splits (reworked glue)
    split_kernel<<<SEQ * DIM / 2048, 256>>>(x, xh, xl);
    wsplit_all_kernel<<<5120, dim3(32, 8)>>>(
        wq, wk, wv, wo, wqh, wql, wkh, wkl, wvh, wvl, woh, wol);

    // fused QKV projection
    qkv_gemm_kernel<<<dim3(24, 16), 256, GEMM_SMEM>>>(
        xh, xl, wqh, wql, wkh, wkl, wvh, wvl,
        qsh, qsl, ksh, ksl, Vb);

    // V transpose-split
    vtsplit_kernel<<<dim3(SEQ / 64, KVDIM / 32), dim3(32, 8)>>>(Vb, vth, vtl);

    // HMMA flash attention (BQ=128, 2 heads / CTA, mt=2)
    attn_mma_kernel<<<dim3(SEQ / BQ, NKV * 2), 256, ATT_SMEM>>>(
        qsh, qsl, ksh, ksl, vth, vtl, Oh, Ol);

    // output projection
    gemm3_kernel<<<dim3(DIM / 128, SEQ / 128), 256, GEMM_SMEM>>>(
        Oh, Ol, woh, wol, out, DIM);
}

// round 15
// speedup vs baseline: 1.0421x; 1.0189x over previous
#include <cuda_runtime.h>
#include <cuda_bf16.h>
#include <cstdint>

// ---------------------------------------------------------------------------
// GroupedQueryAttention — Round 14: GEMMs adopt attention's tile geometry
// (KCH=64, 144B padded rows, 2-stage, 1 CTA/SM). Attention + glue = R13.
// ---------------------------------------------------------------------------

#define SEQ      2048
#define DIM      2048
#define KVDIM    512
#define NHEADS   32
#define NKV      8
#define GROUP    4
#define HDIM     64
#define GK       2048

// fp32 scratch (V only)
__device__ float g_V[SEQ * KVDIM];

// bf16 split scratch
__device__ __nv_bfloat16 g_xh[SEQ * DIM];
__device__ __nv_bfloat16 g_xl[SEQ * DIM];
__device__ __nv_bfloat16 g_Oh[SEQ * DIM];
__device__ __nv_bfloat16 g_Ol[SEQ * DIM];
__device__ __nv_bfloat16 g_wqhT[DIM * DIM];
__device__ __nv_bfloat16 g_wqlT[DIM * DIM];
__device__ __nv_bfloat16 g_wkhT[KVDIM * DIM];
__device__ __nv_bfloat16 g_wklT[KVDIM * DIM];
__device__ __nv_bfloat16 g_wvhT[KVDIM * DIM];
__device__ __nv_bfloat16 g_wvlT[KVDIM * DIM];
__device__ __nv_bfloat16 g_wohT[DIM * DIM];
__device__ __nv_bfloat16 g_wolT[DIM * DIM];

// attention operands
__device__ __nv_bfloat16 g_Qh[SEQ * DIM];     // rope applied, *0.125*log2(e)
__device__ __nv_bfloat16 g_Ql[SEQ * DIM];
__device__ __nv_bfloat16 g_Kh[SEQ * KVDIM];   // rope applied
__device__ __nv_bfloat16 g_Kl[SEQ * KVDIM];
__device__ __nv_bfloat16 g_Vth[KVDIM * SEQ];  // V transposed [512][2048]
__device__ __nv_bfloat16 g_Vtl[KVDIM * SEQ];

// ---------------------------------------------------------------------------
// PTX helpers
// ---------------------------------------------------------------------------
__device__ __forceinline__ uint32_t smem_u32(const void* p) {
    uint32_t a;
    asm("{ .reg .u64 t; cvta.to.shared.u64 t, %1; cvt.u32.u64 %0, t; }"
        : "=r"(a) : "l"(p));
    return a;
}

#define CP_ASYNC16(dst_u32, src_ptr) \
    asm volatile("cp.async.cg.shared.global [%0], [%1], 16;" \
                 :: "r"(dst_u32), "l"(src_ptr))
#define CP_COMMIT() asm volatile("cp.async.commit_group;" ::: "memory")
#define CP_WAIT1()  asm volatile("cp.async.wait_group 1;" ::: "memory")
#define CP_WAIT0()  asm volatile("cp.async.wait_group 0;" ::: "memory")

__device__ __forceinline__ void ldsm_x4(uint32_t* r, uint32_t addr) {
    asm volatile("ldmatrix.sync.aligned.m8n8.x4.shared.b16 {%0,%1,%2,%3}, [%4];"
                 : "=r"(r[0]), "=r"(r[1]), "=r"(r[2]), "=r"(r[3]) : "r"(addr));
}

__device__ __forceinline__ void mma16816(float* c, const uint32_t* a,
                                         const uint32_t* b) {
    asm volatile(
        "mma.sync.aligned.m16n8k16.row.col.f32.bf16.bf16.f32 "
        "{%0,%1,%2,%3}, {%4,%5,%6,%7}, {%8,%9}, {%0,%1,%2,%3};"
        : "+f"(c[0]), "+f"(c[1]), "+f"(c[2]), "+f"(c[3])
        : "r"(a[0]), "r"(a[1]), "r"(a[2]), "r"(a[3]), "r"(b[0]), "r"(b[1]));
}

__device__ __forceinline__ float exp2a(float x) {
    float y;
    asm("ex2.approx.ftz.f32 %0, %1;" : "=f"(y) : "f"(x));
    return y;
}

__device__ __forceinline__ void split2(float a, float b,
                                       uint32_t& hi, uint32_t& lo) {
    __nv_bfloat162 H = __floats2bfloat162_rn(a, b);
    float2 Hf = __bfloat1622float2(H);
    __nv_bfloat162 L = __floats2bfloat162_rn(a - Hf.x, b - Hf.y);
    hi = *reinterpret_cast<uint32_t*>(&H);
    lo = *reinterpret_cast<uint32_t*>(&L);
}

// ---------------------------------------------------------------------------
// GEMM tiling: 128x128 CTA tile, 8 warps (4x2 of 32x64), KCH=64,
// 144B padded rows (attention geometry), 2-stage cp.async, 1 CTA/SM.
// ---------------------------------------------------------------------------
#define KCH      64
#define GPADH    72
#define GROWB    (GPADH * 2)            // 144 bytes per 64-half row
#define GTILE    (128 * GROWB)          // 18432
#define STAGE_B  (4 * GTILE)            // 73728
#define GEMM_SMEM (2 * STAGE_B)         // 147456

__device__ __forceinline__ void issue_stage(
    const __nv_bfloat16* __restrict__ Ah, const __nv_bfloat16* __restrict__ Al,
    const __nv_bfloat16* __restrict__ Bh, const __nv_bfloat16* __restrict__ Bl,
    int m0, int n0, int k0, uint32_t s_u32, int tid)
{
    const __nv_bfloat16* gp[4] = { Ah, Al, Bh, Bl };
    const int r0[4] = { m0, m0, n0, n0 };
    #pragma unroll
    for (int p = 0; p < 4; p++) {
        #pragma unroll
        for (int i = 0; i < 4; i++) {
            int e   = tid + i * 256;          // 0..1023
            int row = e >> 3;                 // 0..127
            int q   = e & 7;                  // 0..7 (16B quads across 128B)
            const __nv_bfloat16* src =
                gp[p] + (size_t)(r0[p] + row) * GK + k0 + q * 8;
            uint32_t dst = s_u32 + p * GTILE + row * GROWB + q * 16;
            CP_ASYNC16(dst, src);
        }
    }
}

__device__ __forceinline__ void gemm_mainloop(
    const __nv_bfloat16* Ah, const __nv_bfloat16* Al,
    const __nv_bfloat16* Bh, const __nv_bfloat16* Bl,
    int m0, int n0, uint32_t sm0, int tid, int wm, int wn,
    int lrow, int lcol, float acc[2][8][4])
{
    const int NC = GK / KCH;   // 32

    issue_stage(Ah, Al, Bh, Bl, m0, n0, 0, sm0, tid);
    CP_COMMIT();

    for (int c = 0; c < NC; c++) {
        if (c + 1 < NC) {
            issue_stage(Ah, Al, Bh, Bl, m0, n0, (c + 1) * KCH,
                        sm0 + ((c + 1) & 1) * STAGE_B, tid);
            CP_COMMIT();
            CP_WAIT1();
        } else {
            CP_WAIT0();
        }
        __syncthreads();

        const uint32_t sb  = sm0 + (c & 1) * STAGE_B;
        const uint32_t sAh = sb + 0 * GTILE;
        const uint32_t sAl = sb + 1 * GTILE;
        const uint32_t sBh = sb + 2 * GTILE;
        const uint32_t sBl = sb + 3 * GTILE;

        #pragma unroll
        for (int kk = 0; kk < 4; kk++) {
            uint32_t ah[2][4], al[2][4];
            #pragma unroll
            for (int mt = 0; mt < 2; mt++) {
                uint32_t off =
                    (uint32_t)((wm * 32 + mt * 16 + lrow) * GROWB
                               + (kk * 16 + lcol) * 2);
                ldsm_x4(ah[mt], sAh + off);
                ldsm_x4(al[mt], sAl + off);
            }
            #pragma unroll
            for (int nt = 0; nt < 4; nt++) {
                uint32_t off =
                    (uint32_t)((wn * 64 + nt * 16 + lrow) * GROWB
                               + (kk * 16 + lcol) * 2);
                uint32_t th[4], tl[4];
                ldsm_x4(th, sBh + off);
                ldsm_x4(tl, sBl + off);
                uint32_t b0h[2] = { th[0], th[2] }, b1h[2] = { th[1], th[3] };
                uint32_t b0l[2] = { tl[0], tl[2] }, b1l[2] = { tl[1], tl[3] };
                #pragma unroll
                for (int mt = 0; mt < 2; mt++) {
                    mma16816(acc[mt][2 * nt],     ah[mt], b0h);
                    mma16816(acc[mt][2 * nt],     ah[mt], b0l);
                    mma16816(acc[mt][2 * nt],     al[mt], b0h);
                    mma16816(acc[mt][2 * nt + 1], ah[mt], b1h);
                    mma16816(acc[mt][2 * nt + 1], ah[mt], b1l);
                    mma16816(acc[mt][2 * nt + 1], al[mt], b1h);
                }
            }
        }
        __syncthreads();
    }
}

// ---------------------------------------------------------------------------
// Fused QKV GEMM (+rope+split epilogues)
// ---------------------------------------------------------------------------
#define LN10K_32  0.2878231366f
#define QSCALE    0.1803368801f    // 0.125 * log2(e)

__global__ void __launch_bounds__(256, 1)
qkv_gemm_kernel(const __nv_bfloat16* __restrict__ xh,
                const __nv_bfloat16* __restrict__ xl,
                const __nv_bfloat16* __restrict__ wqh,
                const __nv_bfloat16* __restrict__ wql,
                const __nv_bfloat16* __restrict__ wkh,
                const __nv_bfloat16* __restrict__ wkl,
                const __nv_bfloat16* __restrict__ wvh,
                const __nv_bfloat16* __restrict__ wvl,
                __nv_bfloat16* __restrict__ Qh, __nv_bfloat16* __restrict__ Ql,
                __nv_bfloat16* __restrict__ Kh, __nv_bfloat16* __restrict__ Kl,
                float* __restrict__ V)
{
    extern __shared__ char smem[];
    const uint32_t sm0 = smem_u32(smem);
    const int tid  = threadIdx.x;
    const int wid  = tid >> 5;
    const int lane = tid & 31;
    const int wm   = wid & 3;
    const int wn   = wid >> 2;
    const int m0   = blockIdx.y * 128;
    const int bx   = blockIdx.x;

    int mode, n0;
    const __nv_bfloat16 *Bh, *Bl;
    if (bx < 16)      { mode = 0; n0 = bx * 128;        Bh = wqh; Bl = wql; }
    else if (bx < 20) { mode = 1; n0 = (bx - 16) * 128; Bh = wkh; Bl = wkl; }
    else              { mode = 2; n0 = (bx - 20) * 128; Bh = wvh; Bl = wvl; }

    const int lrow = (lane & 7) + ((lane >> 3) & 1) * 8;
    const int lcol = (lane >> 4) * 8;

    float acc[2][8][4];
    #pragma unroll
    for (int mt = 0; mt < 2; mt++)
        #pragma unroll
        for (int n8 = 0; n8 < 8; n8++)
            #pragma unroll
            for (int j = 0; j < 4; j++) acc[mt][n8][j] = 0.f;

    gemm_mainloop(xh, xl, Bh, Bl, m0, n0, sm0, tid, wm, wn, lrow, lcol, acc);

    const int cr = lane >> 2;
    const int cc = (lane & 3) * 2;

    if (mode == 2) {
        #pragma unroll
        for (int mt = 0; mt < 2; mt++)
            #pragma unroll
            for (int n8 = 0; n8 < 8; n8++) {
                float* base = V + (size_t)(m0 + wm * 32 + mt * 16 + cr) * KVDIM
                                + n0 + wn * 64 + n8 * 8 + cc;
                *reinterpret_cast<float2*>(base) =
                    make_float2(acc[mt][n8][0], acc[mt][n8][1]);
                *reinterpret_cast<float2*>(base + 8 * (size_t)KVDIM) =
                    make_float2(acc[mt][n8][2], acc[mt][n8][3]);
            }
        return;
    }

    const float scale = (mode == 0) ? QSCALE : 1.0f;
    const int   ldo   = (mode == 0) ? DIM : KVDIM;
    __nv_bfloat16* OH = (mode == 0) ? Qh : Kh;
    __nv_bfloat16* OL = (mode == 0) ? Ql : Kl;

    #pragma unroll
    for (int mt = 0; mt < 2; mt++) {
        const int r0 = m0 + wm * 32 + mt * 16 + cr;
        #pragma unroll
        for (int n8 = 0; n8 < 4; n8++) {
            const int d0 = n8 * 8 + cc;
            const float f0 = __expf(-(float)d0 * LN10K_32);
            const float f1 = __expf(-(float)(d0 + 1) * LN10K_32);
            #pragma unroll
            for (int half = 0; half < 2; half++) {
                const int r = r0 + half * 8;
                float c0, s0, c1, s1;
                sincosf((float)r * f0, &s0, &c0);
                sincosf((float)r * f1, &s1, &c1);
                const float x1a = acc[mt][n8][half * 2 + 0];
                const float x1b = acc[mt][n8][half * 2 + 1];
                const float x2a = acc[mt][n8 + 4][half * 2 + 0];
                const float x2b = acc[mt][n8 + 4][half * 2 + 1];
                const float lo0 = (x1a * c0 - x2a * s0) * scale;
                const float lo1 = (x1b * c1 - x2b * s1) * scale;
                const float hi0 = (x2a * c0 + x1a * s0) * scale;
                const float hi1 = (x2b * c1 + x1b * s1) * scale;
                const size_t off = (size_t)r * ldo + n0 + wn * 64 + n8 * 8 + cc;
                uint32_t H, L;
                split2(lo0, lo1, H, L);
                *reinterpret_cast<uint32_t*>(OH + off) = H;
                *reinterpret_cast<uint32_t*>(OL + off) = L;
                split2(hi0, hi1, H, L);
                *reinterpret_cast<uint32_t*>(OH + off + 32) = H;
                *reinterpret_cast<uint32_t*>(OL + off + 32) = L;
            }
        }
    }
}

// ---------------------------------------------------------------------------
// O-projection GEMM
// ---------------------------------------------------------------------------
__global__ void __launch_bounds__(256, 1)
gemm3_kernel(const __nv_bfloat16* __restrict__ Ah,
             const __nv_bfloat16* __restrict__ Al,
             const __nv_bfloat16* __restrict__ BhT,
             const __nv_bfloat16* __restrict__ BlT,
             float* __restrict__ C, int ldc)
{
    extern __shared__ char smem[];
    const uint32_t sm0 = smem_u32(smem);
    const int tid  = threadIdx.x;
    const int wid  = tid >> 5;
    const int lane = tid & 31;
    const int wm   = wid & 3;
    const int wn   = wid >> 2;
    const int m0   = blockIdx.y * 128;
    const int n0   = blockIdx.x * 128;

    const int lrow = (lane & 7) + ((lane >> 3) & 1) * 8;
    const int lcol = (lane >> 4) * 8;

    float acc[2][8][4];
    #pragma unroll
    for (int mt = 0; mt < 2; mt++)
        #pragma unroll
        for (int n8 = 0; n8 < 8; n8++)
            #pragma unroll
            for (int j = 0; j < 4; j++) acc[mt][n8][j] = 0.f;

    gemm_mainloop(Ah, Al, BhT, BlT, m0, n0, sm0, tid, wm, wn, lrow, lcol, acc);

    const int cr = lane >> 2;
    const int cc = (lane & 3) * 2;
    #pragma unroll
    for (int mt = 0; mt < 2; mt++) {
        #pragma unroll
        for (int n8 = 0; n8 < 8; n8++) {
            float* base = C + (size_t)(m0 + wm * 32 + mt * 16 + cr) * ldc
                            + n0 + wn * 64 + n8 * 8 + cc;
            *reinterpret_cast<float2*>(base) =
                make_float2(acc[mt][n8][0], acc[mt][n8][1]);
            *reinterpret_cast<float2*>(base + 8 * (size_t)ldc) =
                make_float2(acc[mt][n8][2], acc[mt][n8][3]);
        }
    }
}

// ---------------------------------------------------------------------------
// x split — 8 floats per thread
// ---------------------------------------------------------------------------
__global__ void split_kernel(const float* __restrict__ in,
                             __nv_bfloat16* __restrict__ hi,
                             __nv_bfloat16* __restrict__ lo)
{
    int i = (blockIdx.x * 256 + threadIdx.x) * 8;
    float4 v0 = *reinterpret_cast<const float4*>(in + i);
    float4 v1 = *reinterpret_cast<const float4*>(in + i + 4);
    float vv[8] = { v0.x, v0.y, v0.z, v0.w, v1.x, v1.y, v1.z, v1.w };
    __nv_bfloat16 h[8], l[8];
    #pragma unroll
    for (int j = 0; j < 8; j++) {
        h[j] = __float2bfloat16(vv[j]);
        l[j] = __float2bfloat16(vv[j] - __bfloat162float(h[j]));
    }
    *reinterpret_cast<uint4*>(hi + i) = *reinterpret_cast<uint4*>(h);
    *reinterpret_cast<uint4*>(lo + i) = *reinterpret_cast<uint4*>(l);
}

// ---------------------------------------------------------------------------
// Weight transpose-splits, ONE launch — 64(k) x 32(n) tiles, packed bf16x2.
// ---------------------------------------------------------------------------
__global__ void wsplit_all_kernel(
    const float* __restrict__ wq, const float* __restrict__ wk,
    const float* __restrict__ wv, const float* __restrict__ wo,
    __nv_bfloat16* __restrict__ wqh, __nv_bfloat16* __restrict__ wql,
    __nv_bfloat16* __restrict__ wkh, __nv_bfloat16* __restrict__ wkl,
    __nv_bfloat16* __restrict__ wvh, __nv_bfloat16* __restrict__ wvl,
    __nv_bfloat16* __restrict__ woh, __nv_bfloat16* __restrict__ wol)
{
    __shared__ float t[64][33];
    int bid = blockIdx.x;
    const float* w;
    __nv_bfloat16 *hiT, *loT;
    int N, local;
    if (bid < 2048)      { w = wq; hiT = wqh; loT = wql; N = DIM;   local = bid; }
    else if (bid < 2560) { w = wk; hiT = wkh; loT = wkl; N = KVDIM; local = bid - 2048; }
    else if (bid < 3072) { w = wv; hiT = wvh; loT = wvl; N = KVDIM; local = bid - 2560; }
    else                 { w = wo; hiT = woh; loT = wol; N = DIM;   local = bid - 3072; }
    const int nbx = N / 32;
    const int n0 = (local % nbx) * 32;
    const int k0 = (local / nbx) * 64;
    const int tx = threadIdx.x, ty = threadIdx.y;
    #pragma unroll
    for (int r = 0; r < 8; r++)
        t[ty + 8 * r][tx] = w[(size_t)(k0 + ty + 8 * r) * N + n0 + tx];
    __syncthreads();
    #pragma unroll
    for (int j = 0; j < 4; j++) {
        int n = ty + 8 * j;
        float a = t[2 * tx][n];
        float b = t[2 * tx + 1][n];
        uint32_t H, L;
        split2(a, b, H, L);
        size_t o = (size_t)(n0 + n) * GK + k0 + 2 * tx;
        *reinterpret_cast<uint32_t*>(hiT + o) = H;
        *reinterpret_cast<uint32_t*>(loT + o) = L;
    }
}

// ---------------------------------------------------------------------------
// V transpose-split — 64(s) x 32(d) tiles, packed bf16x2
// ---------------------------------------------------------------------------
__global__ void vtsplit_kernel(const float* __restrict__ V,
                               __nv_bfloat16* __restrict__ Vth,
                               __nv_bfloat16* __restrict__ Vtl)
{
    __shared__ float t[64][33];
    const int sB = blockIdx.x * 64;
    const int dB = blockIdx.y * 32;
    const int tx = threadIdx.x, ty = threadIdx.y;
    #pragma unroll
    for (int r = 0; r < 8; r++)
        t[ty + 8 * r][tx] = V[(size_t)(sB + ty + 8 * r) * KVDIM + dB + tx];
    __syncthreads();
    #pragma unroll
    for (int j = 0; j < 4; j++) {
        int d = ty + 8 * j;
        float a = t[2 * tx][d];
        float b = t[2 * tx + 1][d];
        uint32_t H, L;
        split2(a, b, H, L);
        size_t o = (size_t)(dB + d) * SEQ + sB + 2 * tx;
        *reinterpret_cast<uint32_t*>(Vth + o) = H;
        *reinterpret_cast<uint32_t*>(Vtl + o) = L;
    }
}

// ---------------------------------------------------------------------------
// HMMA flash attention — R11/R13 config (unchanged)
// ---------------------------------------------------------------------------
#define BQ     128
#define BK     64
#define PADH   72
#define ROWB   (PADH * 2)          // 144
#define QATILE (128 * ROWB)        // 18432
#define ATILE  (64 * ROWB)         // 9216
#define ASTAGE (4 * ATILE)         // 36864
#define SM_KV  (4 * QATILE)        // 73728
#define ATT_SMEM (SM_KV + 2 * ASTAGE)   // 147456

__device__ __forceinline__ void att_issue(
    uint32_t sb,
    const __nv_bfloat16* __restrict__ Kh, const __nv_bfloat16* __restrict__ Kl,
    const __nv_bfloat16* __restrict__ Vth, const __nv_bfloat16* __restrict__ Vtl,
    int k0, int kh, int tid)
{
    const size_t kbase  = (size_t)kh * HDIM;
    const size_t vtbase = (size_t)kh * HDIM * SEQ;
    const __nv_bfloat16* gp[4] = { Kh, Kl, Vth, Vtl };
    #pragma unroll
    for (int p = 0; p < 4; p++) {
        #pragma unroll
        for (int i = 0; i < 2; i++) {
            int idx = tid + i * 256;
            int r = idx >> 3, q = idx & 7;
            uint32_t so = (uint32_t)(r * ROWB + q * 16);
            const __nv_bfloat16* src = (p < 2)
                ? gp[p] + (size_t)(k0 + r) * KVDIM + kbase + q * 8
                : gp[p] + vtbase + (size_t)r * SEQ + k0 + q * 8;
            CP_ASYNC16(sb + p * ATILE + so, src);
        }
    }
}

__global__ void __launch_bounds__(256, 1)
attn_mma_kernel(const __nv_bfloat16* __restrict__ Qh,
                const __nv_bfloat16* __restrict__ Ql,
                const __nv_bfloat16* __restrict__ Kh,
                const __nv_bfloat16* __restrict__ Kl,
                const __nv_bfloat16* __restrict__ Vth,
                const __nv_bfloat16* __restrict__ Vtl,
                __nv_bfloat16* __restrict__ Ohi,
                __nv_bfloat16* __restrict__ Olo)
{
    extern __shared__ char smem[];
    const uint32_t s0 = smem_u32(smem);
    const int tid = threadIdx.x, wid = tid >> 5, lane = tid & 31;
    const int hd = wid >> 2;
    const int w  = wid & 3;
    const int h  = blockIdx.y * 2 + hd;
    const int kh = blockIdx.y >> 1;
    const int q0 = blockIdx.x * BQ;
    const int lrow = (lane & 7) + ((lane >> 3) & 1) * 8;
    const int lcol = (lane >> 4) * 8;
    const int gr = lane >> 2, tg = lane & 3;
    const int NT = SEQ / BK;

    #pragma unroll
    for (int b = 0; b < 4; b++) {
        const __nv_bfloat16* src = (b & 1) ? Ql : Qh;
        const int hh = blockIdx.y * 2 + (b >> 1);
        #pragma unroll
        for (int i = 0; i < 4; i++) {
            int idx = tid + i * 256;
            int r = idx >> 3, q = idx & 7;
            CP_ASYNC16(s0 + b * QATILE + (uint32_t)(r * ROWB + q * 16),
                       src + (size_t)(q0 + r) * DIM + hh * HDIM + q * 8);
        }
    }
    att_issue(s0 + SM_KV, Kh, Kl, Vth, Vtl, 0, kh, tid);
    CP_COMMIT();
    CP_WAIT0();
    __syncthreads();

    uint32_t qfh[2][4][4], qfl[2][4][4];
    {
        const uint32_t qb = s0 + (hd * 2) * QATILE;
        #pragma unroll
        for (int mt = 0; mt < 2; mt++)
            #pragma unroll
            for (int kc = 0; kc < 4; kc++) {
                uint32_t off = (uint32_t)((w * 32 + mt * 16 + lrow) * ROWB
                                          + (kc * 16 + lcol) * 2);
                ldsm_x4(qfh[mt][kc], qb + off);
                ldsm_x4(qfl[mt][kc], qb + QATILE + off);
            }
    }

    float acc[2][8][4];
    #pragma unroll
    for (int mt = 0; mt < 2; mt++)
        #pragma unroll
        for (int j = 0; j < 8; j++)
            #pragma unroll
            for (int i = 0; i < 4; i++) acc[mt][j][i] = 0.f;
    float lsum[2][2] = { {0.f, 0.f}, {0.f, 0.f} };

    for (int c = 0; c < NT; c++) {
        if (c + 1 < NT) {
            att_issue(s0 + SM_KV + ((c + 1) & 1) * ASTAGE,
                      Kh, Kl, Vth, Vtl, (c + 1) * BK, kh, tid);
            CP_COMMIT();
            CP_WAIT1();
        } else {
            CP_WAIT0();
        }
        __syncthreads();

        const uint32_t sb  = s0 + SM_KV + (c & 1) * ASTAGE;
        const uint32_t sKh = sb + 0 * ATILE;
        const uint32_t sKl = sb + 1 * ATILE;
        const uint32_t sVh = sb + 2 * ATILE;
        const uint32_t sVl = sb + 3 * ATILE;

        float s[2][8][4];
        #pragma unroll
        for (int mt = 0; mt < 2; mt++)
            #pragma unroll
            for (int j = 0; j < 8; j++)
                #pragma unroll
                for (int i = 0; i < 4; i++) s[mt][j][i] = 0.f;

        #pragma unroll
        for (int kc = 0; kc < 4; kc++) {
            #pragma unroll
            for (int nt = 0; nt < 4; nt++) {
                uint32_t off = (uint32_t)((nt * 16 + lrow) * ROWB + (kc * 16 + lcol) * 2);
                uint32_t th[4], tl[4];
                ldsm_x4(th, sKh + off);
                ldsm_x4(tl, sKl + off);
                uint32_t b0h[2] = { th[0], th[2] }, b1h[2] = { th[1], th[3] };
                uint32_t b0l[2] = { tl[0], tl[2] }, b1l[2] = { tl[1], tl[3] };
                #pragma unroll
                for (int mt = 0; mt < 2; mt++) {
                    mma16816(s[mt][2 * nt],     qfh[mt][kc], b0h);
                    mma16816(s[mt][2 * nt],     qfh[mt][kc], b0l);
                    mma16816(s[mt][2 * nt],     qfl[mt][kc], b0h);
                    mma16816(s[mt][2 * nt + 1], qfh[mt][kc], b1h);
                    mma16816(s[mt][2 * nt + 1], qfh[mt][kc], b1l);
                    mma16816(s[mt][2 * nt + 1], qfl[mt][kc], b1h);
                }
            }
        }

        #pragma unroll
        for (int mt = 0; mt < 2; mt++)
            #pragma unroll
            for (int j = 0; j < 8; j++) {
                s[mt][j][0] = exp2a(s[mt][j][0]);
                s[mt][j][1] = exp2a(s[mt][j][1]);
                s[mt][j][2] = exp2a(s[mt][j][2]);
                s[mt][j][3] = exp2a(s[mt][j][3]);
                lsum[mt][0] += s[mt][j][0] + s[mt][j][1];
                lsum[mt][1] += s[mt][j][2] + s[mt][j][3];
            }

        #pragma unroll
        for (int kc = 0; kc < 4; kc++) {
            uint32_t aph[2][4], apl[2][4];
            #pragma unroll
            for (int mt = 0; mt < 2; mt++) {
                split2(s[mt][2 * kc][0],     s[mt][2 * kc][1],     aph[mt][0], apl[mt][0]);
                split2(s[mt][2 * kc][2],     s[mt][2 * kc][3],     aph[mt][1], apl[mt][1]);
                split2(s[mt][2 * kc + 1][0], s[mt][2 * kc + 1][1], aph[mt][2], apl[mt][2]);
                split2(s[mt][2 * kc + 1][2], s[mt][2 * kc + 1][3], aph[mt][3], apl[mt][3]);
            }
            #pragma unroll
            for (int nt = 0; nt < 4; nt++) {
                uint32_t off = (uint32_t)((nt * 16 + lrow) * ROWB + (kc * 16 + lcol) * 2);
                uint32_t th[4], tl[4];
                ldsm_x4(th, sVh + off);
                ldsm_x4(tl, sVl + off);
                uint32_t b0h[2] = { th[0], th[2] }, b1h[2] = { th[1], th[3] };
                uint32_t b0l[2] = { tl[0], tl[2] }, b1l[2] = { tl[1], tl[3] };
                #pragma unroll
                for (int mt = 0; mt < 2; mt++) {
                    mma16816(acc[mt][2 * nt],     aph[mt], b0h);
                    mma16816(acc[mt][2 * nt],     aph[mt], b0l);
                    mma16816(acc[mt][2 * nt],     apl[mt], b0h);
                    mma16816(acc[mt][2 * nt + 1], aph[mt], b1h);
                    mma16816(acc[mt][2 * nt + 1], aph[mt], b1l);
                    mma16816(acc[mt][2 * nt + 1], apl[mt], b1h);
                }
            }
        }
        __syncthreads();
    }

    #pragma unroll
    for (int mt = 0; mt < 2; mt++)
        #pragma unroll
        for (int i = 0; i < 2; i++) {
            lsum[mt][i] += __shfl_xor_sync(0xffffffffu, lsum[mt][i], 1);
            lsum[mt][i] += __shfl_xor_sync(0xffffffffu, lsum[mt][i], 2);
        }

    #pragma unroll
    for (int mt = 0; mt < 2; mt++) {
        const float inv0 = 1.f / lsum[mt][0], inv1 = 1.f / lsum[mt][1];
        #pragma unroll
        for (int j = 0; j < 8; j++) {
            const size_t off0 = (size_t)(q0 + w * 32 + mt * 16 + gr) * DIM
                              + h * HDIM + j * 8 + tg * 2;
            const size_t off1 = off0 + 8 * (size_t)DIM;
            uint32_t H, L;
            split2(acc[mt][j][0] * inv0, acc[mt][j][1] * inv0, H, L);
            *reinterpret_cast<uint32_t*>(Ohi + off0) = H;
            *reinterpret_cast<uint32_t*>(Olo + off0) = L;
            split2(acc[mt][j][2] * inv1, acc[mt][j][3] * inv1, H, L);
            *reinterpret_cast<uint32_t*>(Ohi + off1) = H;
            *reinterpret_cast<uint32_t*>(Olo + off1) = L;
        }
    }
}

// ---------------------------------------------------------------------------
// Launch
// ---------------------------------------------------------------------------
extern "C" void kernel_launch(void* const* d_in, const int* in_sizes, int n_in,
                              void* d_out, int out_size)
{
    const float* x  = (const float*)d_in[0];
    const float* wq = (const float*)d_in[1];
    const float* wk = (const float*)d_in[2];
    const float* wv = (const float*)d_in[3];
    const float* wo = (const float*)d_in[4];
    float* out = (float*)d_out;

    float* Vb;
    cudaGetSymbolAddress((void**)&Vb, g_V);

    __nv_bfloat16 *xh, *xl, *Oh, *Ol;
    __nv_bfloat16 *wqh, *wql, *wkh, *wkl, *wvh, *wvl, *woh, *wol;
    __nv_bfloat16 *qsh, *qsl, *ksh, *ksl, *vth, *vtl;
    cudaGetSymbolAddress((void**)&xh, g_xh);
    cudaGetSymbolAddress((void**)&xl, g_xl);
    cudaGetSymbolAddress((void**)&Oh, g_Oh);
    cudaGetSymbolAddress((void**)&Ol, g_Ol);
    cudaGetSymbolAddress((void**)&wqh, g_wqhT);
    cudaGetSymbolAddress((void**)&wql, g_wqlT);
    cudaGetSymbolAddress((void**)&wkh, g_wkhT);
    cudaGetSymbolAddress((void**)&wkl, g_wklT);
    cudaGetSymbolAddress((void**)&wvh, g_wvhT);
    cudaGetSymbolAddress((void**)&wvl, g_wvlT);
    cudaGetSymbolAddress((void**)&woh, g_wohT);
    cudaGetSymbolAddress((void**)&wol, g_wolT);
    cudaGetSymbolAddress((void**)&qsh, g_Qh);
    cudaGetSymbolAddress((void**)&qsl, g_Ql);
    cudaGetSymbolAddress((void**)&ksh, g_Kh);
    cudaGetSymbolAddress((void**)&ksl, g_Kl);
    cudaGetSymbolAddress((void**)&vth, g_Vth);
    cudaGetSymbolAddress((void**)&vtl, g_Vtl);

    cudaFuncSetAttribute(qkv_gemm_kernel,
        cudaFuncAttributeMaxDynamicSharedMemorySize, GEMM_SMEM);
    cudaFuncSetAttribute(gemm3_kernel,
        cudaFuncAttributeMaxDynamicSharedMemorySize, GEMM_SMEM);
    cudaFuncSetAttribute(attn_mma_kernel,
        cudaFuncAttributeMaxDynamicSharedMemorySize, ATT_SMEM);

    // splits
    split_kernel<<<SEQ * DIM / 2048, 256>>>(x, xh, xl);
    wsplit_all_kernel<<<5120, dim3(32, 8)>>>(
        wq, wk, wv, wo, wqh, wql, wkh, wkl, wvh, wvl, woh, wol);

    // fused QKV projection (KCH=64 geometry)
    qkv_gemm_kernel<<<dim3(24, 16), 256, GEMM_SMEM>>>(
        xh, xl, wqh, wql, wkh, wkl, wvh, wvl,
        qsh, qsl, ksh, ksl, Vb);

    // V transpose-split
    vtsplit_kernel<<<dim3(SEQ / 64, KVDIM / 32), dim3(32, 8)>>>(Vb, vth, vtl);

    // HMMA flash attention
    attn_mma_kernel<<<dim3(SEQ / BQ, NKV * 2), 256, ATT_SMEM>>>(
        qsh, qsl, ksh, ksl, vth, vtl, Oh, Ol);

    // output projection (KCH=64 geometry)
    gemm3_kernel<<<dim3(DIM / 128, SEQ / 128), 256, GEMM_SMEM>>>(
        Oh, Ol, woh, wol, out, DIM);
}